// round 6
// baseline (speedup 1.0000x reference)
#include <cuda_runtime.h>
#include <cuda_bf16.h>
#include <math.h>

// Problem dims
#define ZD   4096
#define HID  1024
#define DEN  100
#define OUT_D 100
#define BATCH 8
#define WIN  512
#define ROWS (BATCH * WIN)      // 4096
#define G3   (3 * HID)          // 3072

// -------- scratch (no allocation allowed; __device__ globals) --------
__device__ float g_X [ (size_t)ROWS * ZD ];    // z @ W_lgssm            (64 MB)
__device__ float g_GI[ (size_t)ROWS * G3 ];    // x @ W_ih + b_ih        (48 MB)
__device__ float g_WhhT[ (size_t)G3 * HID ];   // W_hh transposed        (12 MB)
__device__ float g_H [ (size_t)ROWS * HID ];   // all hidden states      (16 MB)
__device__ float g_D [ (size_t)ROWS * DEN ];   // dense activations      (1.6 MB)
__device__ float g_h [2][BATCH * HID];         // ping-pong hidden state

// ---------------------------------------------------------------------
// init h0 = 0
// ---------------------------------------------------------------------
__global__ void zero_h_kernel() {
    int i = blockIdx.x * 256 + threadIdx.x;
    if (i < BATCH * HID) g_h[0][i] = 0.0f;
}

// ---------------------------------------------------------------------
// transpose W_hh (1024 x 3072) -> g_WhhT (3072 x 1024)
// ---------------------------------------------------------------------
__global__ void transpose_whh_kernel(const float* __restrict__ W) {
    __shared__ float tile[32][33];
    int x = blockIdx.x * 32 + threadIdx.x;      // col in W (0..3071)
    int y0 = blockIdx.y * 32;                   // row in W
    #pragma unroll
    for (int j = threadIdx.y; j < 32; j += 8)
        tile[j][threadIdx.x] = W[(size_t)(y0 + j) * G3 + x];
    __syncthreads();
    int xt  = blockIdx.y * 32 + threadIdx.x;    // col in WT (= W row)
    int yt0 = blockIdx.x * 32;                  // row in WT (= W col)
    #pragma unroll
    for (int j = threadIdx.y; j < 32; j += 8)
        g_WhhT[(size_t)(yt0 + j) * HID + xt] = tile[threadIdx.x][j];
}

// ---------------------------------------------------------------------
// SGEMM: C = A(MxK, row-major) * B(KxN, row-major) + bias[N]
// which==0: A=Aext, C=g_X.  which==1: A=g_X, C=g_GI.
// BM=BN=128, BK=8, 256 threads, 8x8 per thread. M,N multiple of 128, K of 8.
// ---------------------------------------------------------------------
#define BM 128
#define BN 128
#define BK 8
#define TM 8
#define TN 8

__global__ __launch_bounds__(256) void sgemm_kernel(
    int M, int N, int K,
    const float* __restrict__ Aext,
    const float* __restrict__ B,
    const float* __restrict__ bias,
    int which)
{
    const float* A = (which == 0) ? Aext : (const float*)g_X;
    float*       C = (which == 0) ? g_X  : g_GI;

    __shared__ float As[BK][BM];
    __shared__ float Bs[BK][BN];

    const int cRow = blockIdx.y;
    const int cCol = blockIdx.x;
    const int tid  = threadIdx.x;

    // A tile load mapping: 128 rows x 8 cols = 256 float4
    const int aRow = tid >> 1;            // 0..127
    const int aCol = (tid & 1) * 4;       // 0 or 4
    // B tile load mapping: 8 rows x 128 cols = 256 float4
    const int bRow = tid >> 5;            // 0..7
    const int bCol = (tid & 31) * 4;      // 0..124

    const int tx = tid & 15;
    const int ty = tid >> 4;

    float acc[TM][TN];
    #pragma unroll
    for (int i = 0; i < TM; ++i)
        #pragma unroll
        for (int j = 0; j < TN; ++j) acc[i][j] = 0.0f;

    const float* Ab = A + (size_t)cRow * BM * K;
    const float* Bb = B + (size_t)cCol * BN;

    for (int k0 = 0; k0 < K; k0 += BK) {
        float4 a4 = *(const float4*)(Ab + (size_t)aRow * K + k0 + aCol);
        As[aCol + 0][aRow] = a4.x;
        As[aCol + 1][aRow] = a4.y;
        As[aCol + 2][aRow] = a4.z;
        As[aCol + 3][aRow] = a4.w;
        float4 b4 = *(const float4*)(Bb + (size_t)(k0 + bRow) * N + bCol);
        *(float4*)&Bs[bRow][bCol] = b4;
        __syncthreads();

        #pragma unroll
        for (int k = 0; k < BK; ++k) {
            float regA[TM], regB[TN];
            #pragma unroll
            for (int i = 0; i < TM; ++i) regA[i] = As[k][ty * TM + i];
            #pragma unroll
            for (int j = 0; j < TN; ++j) regB[j] = Bs[k][tx * TN + j];
            #pragma unroll
            for (int i = 0; i < TM; ++i)
                #pragma unroll
                for (int j = 0; j < TN; ++j)
                    acc[i][j] = fmaf(regA[i], regB[j], acc[i][j]);
        }
        __syncthreads();
    }

    float* Cb = C + (size_t)cRow * BM * N + (size_t)cCol * BN;
    #pragma unroll
    for (int i = 0; i < TM; ++i) {
        const int row = ty * TM + i;
        #pragma unroll
        for (int j = 0; j < TN; j += 4) {
            const int col = tx * TN + j;
            float4 v;
            v.x = acc[i][j + 0] + bias[cCol * BN + col + 0];
            v.y = acc[i][j + 1] + bias[cCol * BN + col + 1];
            v.z = acc[i][j + 2] + bias[cCol * BN + col + 2];
            v.w = acc[i][j + 3] + bias[cCol * BN + col + 3];
            *(float4*)(Cb + (size_t)row * N + col) = v;
        }
    }
}

// ---------------------------------------------------------------------
// One GRU timestep. grid = 128 blocks x 256 threads (8 warps/block).
// Each warp owns one hidden unit j, computes gh[b][j] for the 3 gates
// (lanes split K, coalesced reads of g_WhhT rows), then the GRU update.
// ---------------------------------------------------------------------
__global__ __launch_bounds__(256) void gru_step_kernel(
    const float* __restrict__ b_hh, int t, int ping)
{
    __shared__ float sh[BATCH * HID];
    const float* __restrict__ h_prev = g_h[ping];
    float* __restrict__ h_next = g_h[ping ^ 1];

    const int tid = threadIdx.x;
    #pragma unroll
    for (int i = tid; i < BATCH * HID; i += 256) sh[i] = h_prev[i];
    __syncthreads();

    const int warp = tid >> 5;
    const int lane = tid & 31;
    const int j = blockIdx.x * 8 + warp;    // hidden unit (0..1023)

    const float* __restrict__ w0 = g_WhhT + (size_t)(0 * HID + j) * HID;
    const float* __restrict__ w1 = g_WhhT + (size_t)(1 * HID + j) * HID;
    const float* __restrict__ w2 = g_WhhT + (size_t)(2 * HID + j) * HID;

    float a0[BATCH], a1[BATCH], a2[BATCH];
    #pragma unroll
    for (int b = 0; b < BATCH; ++b) { a0[b] = 0.f; a1[b] = 0.f; a2[b] = 0.f; }

    #pragma unroll 4
    for (int it = 0; it < HID / 32; ++it) {
        const int k = lane + it * 32;
        const float wr = w0[k];
        const float wu = w1[k];
        const float wn = w2[k];
        #pragma unroll
        for (int b = 0; b < BATCH; ++b) {
            const float hv = sh[b * HID + k];
            a0[b] = fmaf(wr, hv, a0[b]);
            a1[b] = fmaf(wu, hv, a1[b]);
            a2[b] = fmaf(wn, hv, a2[b]);
        }
    }

    // butterfly reduce across the warp
    #pragma unroll
    for (int off = 16; off > 0; off >>= 1) {
        #pragma unroll
        for (int b = 0; b < BATCH; ++b) {
            a0[b] += __shfl_xor_sync(0xffffffffu, a0[b], off);
            a1[b] += __shfl_xor_sync(0xffffffffu, a1[b], off);
            a2[b] += __shfl_xor_sync(0xffffffffu, a2[b], off);
        }
    }

    if (lane < BATCH) {
        const int b = lane;
        const size_t r = (size_t)b * WIN + t;
        const float* gi = g_GI + r * G3;
        const float hr = a0[b] + b_hh[j];
        const float hu = a1[b] + b_hh[HID + j];
        const float hn = a2[b] + b_hh[2 * HID + j];
        const float ir = gi[j];
        const float iu = gi[HID + j];
        const float in_ = gi[2 * HID + j];
        const float rg = 1.0f / (1.0f + expf(-(ir + hr)));
        const float ug = 1.0f / (1.0f + expf(-(iu + hu)));
        const float ng = tanhf(fmaf(rg, hn, in_));
        const float hp = sh[b * HID + j];
        const float hnew = (1.0f - ug) * ng + ug * hp;
        h_next[b * HID + j] = hnew;
        g_H[r * HID + j] = hnew;
    }
}

// ---------------------------------------------------------------------
// D = H(4096x1024) @ W_dense(1024x100) + b_dense ; 8 rows per block
// ---------------------------------------------------------------------
__global__ __launch_bounds__(128) void dense_kernel(
    const float* __restrict__ Wd, const float* __restrict__ bd)
{
    __shared__ float sh[8 * HID];
    const int r0 = blockIdx.x * 8;
    for (int i = threadIdx.x; i < 8 * HID; i += 128)
        sh[i] = g_H[(size_t)r0 * HID + i];
    __syncthreads();

    const int c = threadIdx.x;
    if (c < DEN) {
        float acc[8];
        #pragma unroll
        for (int i = 0; i < 8; ++i) acc[i] = bd[c];
        #pragma unroll 4
        for (int k = 0; k < HID; ++k) {
            const float w = Wd[k * DEN + c];
            #pragma unroll
            for (int i = 0; i < 8; ++i)
                acc[i] = fmaf(sh[i * HID + k], w, acc[i]);
        }
        #pragma unroll
        for (int i = 0; i < 8; ++i)
            g_D[(size_t)(r0 + i) * DEN + c] = acc[i];
    }
}

// ---------------------------------------------------------------------
// mu / softplus(sigma) heads + reparameterized sample ; 16 rows per block
// ---------------------------------------------------------------------
__global__ __launch_bounds__(128) void heads_kernel(
    const float* __restrict__ W_mu, const float* __restrict__ b_mu,
    const float* __restrict__ W_sg, const float* __restrict__ b_sg,
    const float* __restrict__ noise, float* __restrict__ out)
{
    __shared__ float sh[16 * DEN];
    const int r0 = blockIdx.x * 16;
    for (int i = threadIdx.x; i < 16 * DEN; i += 128)
        sh[i] = g_D[(size_t)r0 * DEN + i];
    __syncthreads();

    const int c = threadIdx.x;
    if (c < OUT_D) {
        float am[16], as[16];
        #pragma unroll
        for (int i = 0; i < 16; ++i) { am[i] = b_mu[c]; as[i] = b_sg[c]; }
        #pragma unroll 2
        for (int k = 0; k < DEN; ++k) {
            const float wm = W_mu[k * OUT_D + c];
            const float ws = W_sg[k * OUT_D + c];
            #pragma unroll
            for (int i = 0; i < 16; ++i) {
                const float d = sh[i * DEN + k];
                am[i] = fmaf(d, wm, am[i]);
                as[i] = fmaf(d, ws, as[i]);
            }
        }
        #pragma unroll
        for (int i = 0; i < 16; ++i) {
            const size_t r = (size_t)(r0 + i);
            const float x = as[i];
            // numerically stable softplus: max(x,0) + log1p(exp(-|x|))
            const float sp = fmaxf(x, 0.0f) + log1pf(expf(-fabsf(x)));
            out[r * OUT_D + c] = fmaf(sp, noise[r * OUT_D + c], am[i]);
        }
    }
}

// ---------------------------------------------------------------------
extern "C" void kernel_launch(void* const* d_in, const int* in_sizes, int n_in,
                              void* d_out, int out_size)
{
    const float* z        = (const float*)d_in[0];
    const float* noise    = (const float*)d_in[1];
    const float* W_lgssm  = (const float*)d_in[2];
    const float* b_lgssm  = (const float*)d_in[3];
    const float* W_ih     = (const float*)d_in[4];
    const float* b_ih     = (const float*)d_in[5];
    const float* W_hh     = (const float*)d_in[6];
    const float* b_hh     = (const float*)d_in[7];
    const float* W_dense  = (const float*)d_in[8];
    const float* b_dense  = (const float*)d_in[9];
    const float* W_mu     = (const float*)d_in[10];
    const float* b_mu     = (const float*)d_in[11];
    const float* W_sigma  = (const float*)d_in[12];
    const float* b_sigma  = (const float*)d_in[13];
    float* out = (float*)d_out;

    // init h0 and transpose W_hh
    zero_h_kernel<<<(BATCH * HID + 255) / 256, 256>>>();
    transpose_whh_kernel<<<dim3(G3 / 32, HID / 32), dim3(32, 8)>>>(W_hh);

    // hoisted input-path GEMMs: X = z @ W_lgssm + b_lgssm ; GI = X @ W_ih + b_ih
    sgemm_kernel<<<dim3(ZD / BN, ROWS / BM), 256>>>(ROWS, ZD, ZD, z, W_lgssm, b_lgssm, 0);
    sgemm_kernel<<<dim3(G3 / BN, ROWS / BM), 256>>>(ROWS, G3, ZD, nullptr, W_ih, b_ih, 1);

    // sequential GRU scan (512 graph nodes)
    for (int t = 0; t < WIN; ++t)
        gru_step_kernel<<<HID / 8, 256>>>(b_hh, t, t & 1);

    // deferred output path
    dense_kernel<<<ROWS / 8, 128>>>(W_dense, b_dense);
    heads_kernel<<<ROWS / 16, 128>>>(W_mu, b_mu, W_sigma, b_sigma, noise, out);
}

// round 8
// speedup vs baseline: 1.6938x; 1.6938x over previous
#include <cuda_runtime.h>
#include <cuda_bf16.h>
#include <math.h>
#include <stdint.h>

// Problem dims
#define ZD   4096
#define HID  1024
#define DEN  100
#define OUT_D 100
#define BATCH 8
#define WIN  512
#define ROWS (BATCH * WIN)      // 4096
#define G3   (3 * HID)          // 3072

// ---------------- scratch (__device__ globals; no allocation allowed) ------
__device__ __nv_bfloat16 g_zhi [ (size_t)ROWS * ZD ];
__device__ __nv_bfloat16 g_zlo [ (size_t)ROWS * ZD ];
__device__ __nv_bfloat16 g_WlgT_hi[ (size_t)ZD * ZD ];   // (N=4096) x (K=4096)
__device__ __nv_bfloat16 g_WlgT_lo[ (size_t)ZD * ZD ];
__device__ __nv_bfloat16 g_WihT_hi[ (size_t)G3 * ZD ];   // (N=3072) x (K=4096)
__device__ __nv_bfloat16 g_WihT_lo[ (size_t)G3 * ZD ];
__device__ __nv_bfloat16 g_Xhi [ (size_t)ROWS * ZD ];    // X = z@W_lgssm + b
__device__ __nv_bfloat16 g_Xlo [ (size_t)ROWS * ZD ];
__device__ float g_GI  [ (size_t)ROWS * G3 ];            // X@W_ih + b_ih (fp32)
__device__ float g_WhhT[ (size_t)G3 * HID ];
__device__ float g_H   [ (size_t)ROWS * HID ];
__device__ float g_D   [ (size_t)ROWS * DEN ];
__device__ float g_h   [2][BATCH * HID];

// ---------------- helpers ---------------------------------------------------
__device__ __forceinline__ uint32_t smem_u32(const void* p) {
    uint32_t a;
    asm("{ .reg .u64 t; cvta.to.shared.u64 t, %1; cvt.u32.u64 %0, t; }"
        : "=r"(a) : "l"(p));
    return a;
}
__device__ __forceinline__ void cp16(uint32_t dst, const void* src) {
    asm volatile(
        "{ .reg .u64 g; cvta.to.global.u64 g, %1; "
        "cp.async.cg.shared.global [%0], [g], 16; }"
        :: "r"(dst), "l"(src) : "memory");
}
__device__ __forceinline__ void cp_commit() {
    asm volatile("cp.async.commit_group;" ::: "memory");
}
template <int N>
__device__ __forceinline__ void cp_wait() {
    asm volatile("cp.async.wait_group %0;" :: "n"(N) : "memory");
}
__device__ __forceinline__ void ldsm_x4(uint32_t* r, uint32_t addr) {
    asm volatile("ldmatrix.sync.aligned.m8n8.x4.shared.b16 {%0,%1,%2,%3}, [%4];"
        : "=r"(r[0]), "=r"(r[1]), "=r"(r[2]), "=r"(r[3]) : "r"(addr));
}
__device__ __forceinline__ void mma16816(float* d, const uint32_t* a,
                                         uint32_t b0, uint32_t b1) {
    asm volatile(
        "mma.sync.aligned.m16n8k16.row.col.f32.bf16.bf16.f32 "
        "{%0,%1,%2,%3}, {%4,%5,%6,%7}, {%8,%9}, {%0,%1,%2,%3};"
        : "+f"(d[0]), "+f"(d[1]), "+f"(d[2]), "+f"(d[3])
        : "r"(a[0]), "r"(a[1]), "r"(a[2]), "r"(a[3]), "r"(b0), "r"(b1));
}

// ---------------- init / conversion kernels --------------------------------
__global__ void zero_h_kernel() {
    int i = blockIdx.x * 256 + threadIdx.x;
    if (i < BATCH * HID) g_h[0][i] = 0.0f;
}

__global__ __launch_bounds__(256) void conv_split_kernel(
    const float* __restrict__ src, __nv_bfloat16* __restrict__ hi,
    __nv_bfloat16* __restrict__ lo, int n)
{
    for (int i = blockIdx.x * 256 + threadIdx.x; i < n; i += gridDim.x * 256) {
        float x = src[i];
        __nv_bfloat16 h = __float2bfloat16(x);
        hi[i] = h;
        lo[i] = __float2bfloat16(x - __bfloat162float(h));
    }
}

// transpose (K x N fp32) -> (N x K bf16 hi/lo)
__global__ __launch_bounds__(256) void transpose_split_kernel(
    const float* __restrict__ W, __nv_bfloat16* __restrict__ Thi,
    __nv_bfloat16* __restrict__ Tlo, int K, int N)
{
    __shared__ float tile[32][33];
    int tx = threadIdx.x, ty = threadIdx.y;
    int x = blockIdx.x * 32 + tx;
    int y0 = blockIdx.y * 32;
    #pragma unroll
    for (int j = ty; j < 32; j += 8)
        tile[j][tx] = W[(size_t)(y0 + j) * N + x];
    __syncthreads();
    int k = blockIdx.y * 32 + tx;
    int n0 = blockIdx.x * 32;
    #pragma unroll
    for (int j = ty; j < 32; j += 8) {
        float v = tile[tx][j];
        __nv_bfloat16 h = __float2bfloat16(v);
        size_t o = (size_t)(n0 + j) * K + k;
        Thi[o] = h;
        Tlo[o] = __float2bfloat16(v - __bfloat162float(h));
    }
}

__global__ void transpose_whh_kernel(const float* __restrict__ W) {
    __shared__ float tile[32][33];
    int x = blockIdx.x * 32 + threadIdx.x;
    int y0 = blockIdx.y * 32;
    #pragma unroll
    for (int j = threadIdx.y; j < 32; j += 8)
        tile[j][threadIdx.x] = W[(size_t)(y0 + j) * G3 + x];
    __syncthreads();
    int xt  = blockIdx.y * 32 + threadIdx.x;
    int yt0 = blockIdx.x * 32;
    #pragma unroll
    for (int j = threadIdx.y; j < 32; j += 8)
        g_WhhT[(size_t)(yt0 + j) * HID + xt] = tile[threadIdx.x][j];
}

// ---------------- split-bf16 mma.sync GEMM ----------------------------------
// C(128x128/CTA) = A(M x 4096) @ BT(N x 4096)^T, A,B each split hi/lo.
// 3 passes into one fp32 accumulator: AhBh + AhBl + AlBh.
// which==0: epilogue -> g_Xhi/g_Xlo (+bias). which==1: -> g_GI fp32 (+bias).
#define MMK       ZD               // 4096, both GEMMs
#define BKC       32               // K per stage (bf16)
#define NC        (MMK / BKC)      // 128 chunks
#define ROWB      80               // smem row stride bytes (40 bf16, conflict-free)
#define TILEB     (128 * ROWB)     // 10240 B per 128x32 tile
#define STAGEB    (4 * TILEB)      // Ah, Al, Bh, Bl
#define NSTAGE    3
#define MM_SMEM   (NSTAGE * STAGEB)  // 122880

__global__ __launch_bounds__(256) void mm_mma_kernel(
    const __nv_bfloat16* __restrict__ Ahi, const __nv_bfloat16* __restrict__ Alo,
    const __nv_bfloat16* __restrict__ Bhi, const __nv_bfloat16* __restrict__ Blo,
    const float* __restrict__ bias, int Nglob, int which)
{
    extern __shared__ char smem[];
    const uint32_t sb = smem_u32(smem);
    const int tid  = threadIdx.x;
    const int wid  = tid >> 5;
    const int lane = tid & 31;
    const int wm   = wid & 3;          // 4 m-blocks of 32
    const int wn   = wid >> 2;         // 2 n-blocks of 64

    const size_t mBase = (size_t)blockIdx.y * 128;
    const size_t nBase = (size_t)blockIdx.x * 128;

    const __nv_bfloat16* tp[4] = { Ahi, Alo, Bhi, Blo };
    const size_t         rb[4] = { mBase, mBase, nBase, nBase };

    // issue one stage's loads (2048 x 16B, 8 per thread)
    auto issue = [&](int chunk, int stage) {
        const size_t kB = (size_t)chunk * BKC;
        const uint32_t stB = sb + stage * STAGEB;
        #pragma unroll
        for (int i = 0; i < 8; ++i) {
            int u    = tid + 256 * i;
            int tile = u >> 9;
            int idx  = u & 511;
            int row  = idx >> 2;
            int seg  = idx & 3;
            const __nv_bfloat16* src = tp[tile] + (rb[tile] + row) * MMK + kB + seg * 8;
            cp16(stB + tile * TILEB + row * ROWB + seg * 16, src);
        }
    };

    float acc[2][8][4];
    #pragma unroll
    for (int a = 0; a < 2; ++a)
        #pragma unroll
        for (int b = 0; b < 8; ++b)
            #pragma unroll
            for (int c = 0; c < 4; ++c) acc[a][b][c] = 0.0f;

    // prologue: fill the pipeline
    issue(0, 0); cp_commit();
    issue(1, 1); cp_commit();
    issue(2, 2); cp_commit();
    cp_wait<2>();
    __syncthreads();

    // fragment address lane math (byte offsets within a tile)
    const int arow = wm * 32 + (lane & 7) + 8 * ((lane >> 3) & 1);
    const int brow = wn * 64 + (lane & 7) + 8 * (lane >> 4);
    const int acol_half = lane >> 4;          // 0/1 -> +8 k
    const int bcol_half = (lane >> 3) & 1;    // 0/1 -> +8 k

    for (int c = 0; c < NC; ++c) {
        const uint32_t stB = sb + (c % NSTAGE) * STAGEB;
        #pragma unroll
        for (int pass = 0; pass < 3; ++pass) {
            const uint32_t Ab = stB + ((pass == 2) ? TILEB : 0);
            const uint32_t Bb = stB + 2 * TILEB + ((pass == 1) ? TILEB : 0);
            #pragma unroll
            for (int ks = 0; ks < 2; ++ks) {
                const int k0 = 16 * ks;
                uint32_t a0[4], a1[4];
                const uint32_t acolb = (uint32_t)(k0 + 8 * acol_half) * 2;
                ldsm_x4(a0, Ab + (uint32_t)arow * ROWB + acolb);
                ldsm_x4(a1, Ab + (uint32_t)(arow + 16) * ROWB + acolb);
                const uint32_t bcolb = (uint32_t)(k0 + 8 * bcol_half) * 2;
                #pragma unroll
                for (int nb = 0; nb < 4; ++nb) {
                    uint32_t bf[4];
                    ldsm_x4(bf, Bb + (uint32_t)(brow + nb * 16) * ROWB + bcolb);
                    mma16816(acc[0][2 * nb],     a0, bf[0], bf[1]);
                    mma16816(acc[0][2 * nb + 1], a0, bf[2], bf[3]);
                    mma16816(acc[1][2 * nb],     a1, bf[0], bf[1]);
                    mma16816(acc[1][2 * nb + 1], a1, bf[2], bf[3]);
                }
            }
        }
        __syncthreads();                 // everyone done reading this stage
        if (c + NSTAGE < NC) issue(c + NSTAGE, c % NSTAGE);
        cp_commit();                     // empty group if nothing issued
        cp_wait<2>();                    // stage (c+1) guaranteed complete
        __syncthreads();
    }

    // epilogue: fragment layout -> global
    const int rrow = (lane >> 2);
    const int ccol = 2 * (lane & 3);
    #pragma unroll
    for (int mi = 0; mi < 2; ++mi) {
        const size_t r0 = mBase + wm * 32 + mi * 16 + rrow;
        #pragma unroll
        for (int n8 = 0; n8 < 8; ++n8) {
            const int col = (int)nBase + wn * 64 + n8 * 8 + ccol;
            const float bz0 = __ldg(&bias[col]);
            const float bz1 = __ldg(&bias[col + 1]);
            const float* f = acc[mi][n8];
            if (which == 0) {
                #pragma unroll
                for (int h = 0; h < 2; ++h) {    // h=0: row r0, h=1: row r0+8
                    const size_t r = r0 + 8 * h;
                    float v0 = f[2 * h]     + bz0;
                    float v1 = f[2 * h + 1] + bz1;
                    __nv_bfloat16 h0 = __float2bfloat16(v0);
                    __nv_bfloat16 h1 = __float2bfloat16(v1);
                    __nv_bfloat16 l0 = __float2bfloat16(v0 - __bfloat162float(h0));
                    __nv_bfloat16 l1 = __float2bfloat16(v1 - __bfloat162float(h1));
                    uint32_t hp = ((uint32_t)__bfloat16_as_ushort(h1) << 16) |
                                  (uint32_t)__bfloat16_as_ushort(h0);
                    uint32_t lp = ((uint32_t)__bfloat16_as_ushort(l1) << 16) |
                                  (uint32_t)__bfloat16_as_ushort(l0);
                    *(uint32_t*)&g_Xhi[r * (size_t)Nglob + col] = hp;
                    *(uint32_t*)&g_Xlo[r * (size_t)Nglob + col] = lp;
                }
            } else {
                #pragma unroll
                for (int h = 0; h < 2; ++h) {
                    const size_t r = r0 + 8 * h;
                    float2 v = make_float2(f[2 * h] + bz0, f[2 * h + 1] + bz1);
                    *(float2*)&g_GI[r * (size_t)Nglob + col] = v;
                }
            }
        }
    }
}

// ---------------- GRU scan (unchanged from passing R6 baseline) ------------
__global__ __launch_bounds__(256) void gru_step_kernel(
    const float* __restrict__ b_hh, int t, int ping)
{
    __shared__ float sh[BATCH * HID];
    const float* __restrict__ h_prev = g_h[ping];
    float* __restrict__ h_next = g_h[ping ^ 1];

    const int tid = threadIdx.x;
    #pragma unroll
    for (int i = tid; i < BATCH * HID; i += 256) sh[i] = h_prev[i];
    __syncthreads();

    const int warp = tid >> 5;
    const int lane = tid & 31;
    const int j = blockIdx.x * 8 + warp;

    const float* __restrict__ w0 = g_WhhT + (size_t)(0 * HID + j) * HID;
    const float* __restrict__ w1 = g_WhhT + (size_t)(1 * HID + j) * HID;
    const float* __restrict__ w2 = g_WhhT + (size_t)(2 * HID + j) * HID;

    float a0[BATCH], a1[BATCH], a2[BATCH];
    #pragma unroll
    for (int b = 0; b < BATCH; ++b) { a0[b] = 0.f; a1[b] = 0.f; a2[b] = 0.f; }

    #pragma unroll 4
    for (int it = 0; it < HID / 32; ++it) {
        const int k = lane + it * 32;
        const float wr = w0[k];
        const float wu = w1[k];
        const float wn = w2[k];
        #pragma unroll
        for (int b = 0; b < BATCH; ++b) {
            const float hv = sh[b * HID + k];
            a0[b] = fmaf(wr, hv, a0[b]);
            a1[b] = fmaf(wu, hv, a1[b]);
            a2[b] = fmaf(wn, hv, a2[b]);
        }
    }

    #pragma unroll
    for (int off = 16; off > 0; off >>= 1) {
        #pragma unroll
        for (int b = 0; b < BATCH; ++b) {
            a0[b] += __shfl_xor_sync(0xffffffffu, a0[b], off);
            a1[b] += __shfl_xor_sync(0xffffffffu, a1[b], off);
            a2[b] += __shfl_xor_sync(0xffffffffu, a2[b], off);
        }
    }

    if (lane < BATCH) {
        const int b = lane;
        const size_t r = (size_t)b * WIN + t;
        const float* gi = g_GI + r * G3;
        const float hr = a0[b] + b_hh[j];
        const float hu = a1[b] + b_hh[HID + j];
        const float hn = a2[b] + b_hh[2 * HID + j];
        const float ir = gi[j];
        const float iu = gi[HID + j];
        const float in_ = gi[2 * HID + j];
        const float rg = 1.0f / (1.0f + expf(-(ir + hr)));
        const float ug = 1.0f / (1.0f + expf(-(iu + hu)));
        const float ng = tanhf(fmaf(rg, hn, in_));
        const float hp = sh[b * HID + j];
        const float hnew = (1.0f - ug) * ng + ug * hp;
        h_next[b * HID + j] = hnew;
        g_H[r * HID + j] = hnew;
    }
}

// ---------------- dense + heads (unchanged) --------------------------------
__global__ __launch_bounds__(128) void dense_kernel(
    const float* __restrict__ Wd, const float* __restrict__ bd)
{
    __shared__ float sh[8 * HID];
    const int r0 = blockIdx.x * 8;
    for (int i = threadIdx.x; i < 8 * HID; i += 128)
        sh[i] = g_H[(size_t)r0 * HID + i];
    __syncthreads();

    const int c = threadIdx.x;
    if (c < DEN) {
        float acc[8];
        #pragma unroll
        for (int i = 0; i < 8; ++i) acc[i] = bd[c];
        #pragma unroll 4
        for (int k = 0; k < HID; ++k) {
            const float w = Wd[k * DEN + c];
            #pragma unroll
            for (int i = 0; i < 8; ++i)
                acc[i] = fmaf(sh[i * HID + k], w, acc[i]);
        }
        #pragma unroll
        for (int i = 0; i < 8; ++i)
            g_D[(size_t)(r0 + i) * DEN + c] = acc[i];
    }
}

__global__ __launch_bounds__(128) void heads_kernel(
    const float* __restrict__ W_mu, const float* __restrict__ b_mu,
    const float* __restrict__ W_sg, const float* __restrict__ b_sg,
    const float* __restrict__ noise, float* __restrict__ out)
{
    __shared__ float sh[16 * DEN];
    const int r0 = blockIdx.x * 16;
    for (int i = threadIdx.x; i < 16 * DEN; i += 128)
        sh[i] = g_D[(size_t)r0 * DEN + i];
    __syncthreads();

    const int c = threadIdx.x;
    if (c < OUT_D) {
        float am[16], as[16];
        #pragma unroll
        for (int i = 0; i < 16; ++i) { am[i] = b_mu[c]; as[i] = b_sg[c]; }
        #pragma unroll 2
        for (int k = 0; k < DEN; ++k) {
            const float wm = W_mu[k * OUT_D + c];
            const float ws = W_sg[k * OUT_D + c];
            #pragma unroll
            for (int i = 0; i < 16; ++i) {
                const float d = sh[i * DEN + k];
                am[i] = fmaf(d, wm, am[i]);
                as[i] = fmaf(d, ws, as[i]);
            }
        }
        #pragma unroll
        for (int i = 0; i < 16; ++i) {
            const size_t r = (size_t)(r0 + i);
            const float x = as[i];
            const float sp = fmaxf(x, 0.0f) + log1pf(expf(-fabsf(x)));
            out[r * OUT_D + c] = fmaf(sp, noise[r * OUT_D + c], am[i]);
        }
    }
}

// ---------------------------------------------------------------------------
extern "C" void kernel_launch(void* const* d_in, const int* in_sizes, int n_in,
                              void* d_out, int out_size)
{
    const float* z        = (const float*)d_in[0];
    const float* noise    = (const float*)d_in[1];
    const float* W_lgssm  = (const float*)d_in[2];
    const float* b_lgssm  = (const float*)d_in[3];
    const float* W_ih     = (const float*)d_in[4];
    const float* b_ih     = (const float*)d_in[5];
    const float* W_hh     = (const float*)d_in[6];
    const float* b_hh     = (const float*)d_in[7];
    const float* W_dense  = (const float*)d_in[8];
    const float* b_dense  = (const float*)d_in[9];
    const float* W_mu     = (const float*)d_in[10];
    const float* b_mu     = (const float*)d_in[11];
    const float* W_sigma  = (const float*)d_in[12];
    const float* b_sigma  = (const float*)d_in[13];
    float* out = (float*)d_out;

    static int attr_done = 0;
    if (!attr_done) {
        cudaFuncSetAttribute(mm_mma_kernel,
                             cudaFuncAttributeMaxDynamicSharedMemorySize, MM_SMEM);
        attr_done = 1;
    }

    __nv_bfloat16 *p_zhi, *p_zlo, *p_Wlg_hi, *p_Wlg_lo, *p_Wih_hi, *p_Wih_lo;
    __nv_bfloat16 *p_Xhi, *p_Xlo;
    cudaGetSymbolAddress((void**)&p_zhi,    g_zhi);
    cudaGetSymbolAddress((void**)&p_zlo,    g_zlo);
    cudaGetSymbolAddress((void**)&p_Wlg_hi, g_WlgT_hi);
    cudaGetSymbolAddress((void**)&p_Wlg_lo, g_WlgT_lo);
    cudaGetSymbolAddress((void**)&p_Wih_hi, g_WihT_hi);
    cudaGetSymbolAddress((void**)&p_Wih_lo, g_WihT_lo);
    cudaGetSymbolAddress((void**)&p_Xhi,    g_Xhi);
    cudaGetSymbolAddress((void**)&p_Xlo,    g_Xlo);

    // init + conversions
    zero_h_kernel<<<(BATCH * HID + 255) / 256, 256>>>();
    transpose_whh_kernel<<<dim3(G3 / 32, HID / 32), dim3(32, 8)>>>(W_hh);
    conv_split_kernel<<<2048, 256>>>(z, p_zhi, p_zlo, ROWS * ZD);
    transpose_split_kernel<<<dim3(ZD / 32, ZD / 32), dim3(32, 8)>>>(
        W_lgssm, p_Wlg_hi, p_Wlg_lo, ZD, ZD);
    transpose_split_kernel<<<dim3(G3 / 32, ZD / 32), dim3(32, 8)>>>(
        W_ih, p_Wih_hi, p_Wih_lo, ZD, G3);

    // GEMM1: X = z @ W_lgssm + b_lgssm -> bf16 hi/lo split
    mm_mma_kernel<<<dim3(ZD / 128, ROWS / 128), 256, MM_SMEM>>>(
        p_zhi, p_zlo, p_Wlg_hi, p_Wlg_lo, b_lgssm, ZD, 0);
    // GEMM2: GI = X @ W_ih + b_ih -> fp32
    mm_mma_kernel<<<dim3(G3 / 128, ROWS / 128), 256, MM_SMEM>>>(
        p_Xhi, p_Xlo, p_Wih_hi, p_Wih_lo, b_ih, G3, 1);

    // sequential GRU scan
    for (int t = 0; t < WIN; ++t)
        gru_step_kernel<<<HID / 8, 256>>>(b_hh, t, t & 1);

    // deferred output path
    dense_kernel<<<ROWS / 8, 128>>>(W_dense, b_dense);
    heads_kernel<<<ROWS / 16, 128>>>(W_mu, b_mu, W_sigma, b_sigma, noise, out);
}

// round 9
// speedup vs baseline: 1.7320x; 1.0225x over previous
#include <cuda_runtime.h>
#include <cuda_bf16.h>
#include <math.h>
#include <stdint.h>

// Problem dims
#define ZD   4096
#define HID  1024
#define DEN  100
#define OUT_D 100
#define BATCH 8
#define WIN  512
#define ROWS (BATCH * WIN)      // 4096
#define G3   (3 * HID)          // 3072

// ---------------- scratch (__device__ globals; no allocation allowed) ------
__device__ __nv_bfloat16 g_zhi [ (size_t)ROWS * ZD ];
__device__ __nv_bfloat16 g_zlo [ (size_t)ROWS * ZD ];
__device__ __nv_bfloat16 g_WlgT_hi[ (size_t)ZD * ZD ];   // (N=4096) x (K=4096)
__device__ __nv_bfloat16 g_WlgT_lo[ (size_t)ZD * ZD ];
__device__ __nv_bfloat16 g_WihT_hi[ (size_t)G3 * ZD ];   // (N=3072) x (K=4096)
__device__ __nv_bfloat16 g_WihT_lo[ (size_t)G3 * ZD ];
__device__ __nv_bfloat16 g_Xhi [ (size_t)ROWS * ZD ];    // X = z@W_lgssm + b
__device__ __nv_bfloat16 g_Xlo [ (size_t)ROWS * ZD ];
__device__ float g_GI  [ (size_t)ROWS * G3 ];            // X@W_ih + b_ih (fp32)
__device__ float g_WhhT[ (size_t)G3 * HID ];
__device__ float g_H   [ (size_t)ROWS * HID ];
__device__ float g_D   [ (size_t)ROWS * DEN ];
__device__ float g_hT  [2][HID * BATCH];                 // ping-pong h, [k][b]

// grid-barrier state for the persistent scan
#define NCTA_SCAN 128
__device__ unsigned g_bar_ctr = 0;
__device__ volatile unsigned g_bar_flag = 0;

// ---------------- helpers ---------------------------------------------------
__device__ __forceinline__ uint32_t smem_u32(const void* p) {
    uint32_t a;
    asm("{ .reg .u64 t; cvta.to.shared.u64 t, %1; cvt.u32.u64 %0, t; }"
        : "=r"(a) : "l"(p));
    return a;
}
__device__ __forceinline__ void cp16(uint32_t dst, const void* src) {
    asm volatile(
        "{ .reg .u64 g; cvta.to.global.u64 g, %1; "
        "cp.async.cg.shared.global [%0], [g], 16; }"
        :: "r"(dst), "l"(src) : "memory");
}
__device__ __forceinline__ void cp_commit() {
    asm volatile("cp.async.commit_group;" ::: "memory");
}
template <int N>
__device__ __forceinline__ void cp_wait() {
    asm volatile("cp.async.wait_group %0;" :: "n"(N) : "memory");
}
__device__ __forceinline__ void ldsm_x4(uint32_t* r, uint32_t addr) {
    asm volatile("ldmatrix.sync.aligned.m8n8.x4.shared.b16 {%0,%1,%2,%3}, [%4];"
        : "=r"(r[0]), "=r"(r[1]), "=r"(r[2]), "=r"(r[3]) : "r"(addr));
}
__device__ __forceinline__ void mma16816(float* d, const uint32_t* a,
                                         uint32_t b0, uint32_t b1) {
    asm volatile(
        "mma.sync.aligned.m16n8k16.row.col.f32.bf16.bf16.f32 "
        "{%0,%1,%2,%3}, {%4,%5,%6,%7}, {%8,%9}, {%0,%1,%2,%3};"
        : "+f"(d[0]), "+f"(d[1]), "+f"(d[2]), "+f"(d[3])
        : "r"(a[0]), "r"(a[1]), "r"(a[2]), "r"(a[3]), "r"(b0), "r"(b1));
}

// ---------------- conversion kernels ---------------------------------------
__global__ __launch_bounds__(256) void conv_split_kernel(
    const float* __restrict__ src, __nv_bfloat16* __restrict__ hi,
    __nv_bfloat16* __restrict__ lo, int n)
{
    for (int i = blockIdx.x * 256 + threadIdx.x; i < n; i += gridDim.x * 256) {
        float x = src[i];
        __nv_bfloat16 h = __float2bfloat16(x);
        hi[i] = h;
        lo[i] = __float2bfloat16(x - __bfloat162float(h));
    }
}

// transpose (K x N fp32) -> (N x K bf16 hi/lo)
__global__ __launch_bounds__(256) void transpose_split_kernel(
    const float* __restrict__ W, __nv_bfloat16* __restrict__ Thi,
    __nv_bfloat16* __restrict__ Tlo, int K, int N)
{
    __shared__ float tile[32][33];
    int tx = threadIdx.x, ty = threadIdx.y;
    int x = blockIdx.x * 32 + tx;
    int y0 = blockIdx.y * 32;
    #pragma unroll
    for (int j = ty; j < 32; j += 8)
        tile[j][tx] = W[(size_t)(y0 + j) * N + x];
    __syncthreads();
    int k = blockIdx.y * 32 + tx;
    int n0 = blockIdx.x * 32;
    #pragma unroll
    for (int j = ty; j < 32; j += 8) {
        float v = tile[tx][j];
        __nv_bfloat16 h = __float2bfloat16(v);
        size_t o = (size_t)(n0 + j) * K + k;
        Thi[o] = h;
        Tlo[o] = __float2bfloat16(v - __bfloat162float(h));
    }
}

__global__ void transpose_whh_kernel(const float* __restrict__ W) {
    __shared__ float tile[32][33];
    int x = blockIdx.x * 32 + threadIdx.x;
    int y0 = blockIdx.y * 32;
    #pragma unroll
    for (int j = threadIdx.y; j < 32; j += 8)
        tile[j][threadIdx.x] = W[(size_t)(y0 + j) * G3 + x];
    __syncthreads();
    int xt  = blockIdx.y * 32 + threadIdx.x;
    int yt0 = blockIdx.x * 32;
    #pragma unroll
    for (int j = threadIdx.y; j < 32; j += 8)
        g_WhhT[(size_t)(yt0 + j) * HID + xt] = tile[threadIdx.x][j];
}

// ---------------- split-bf16 mma.sync GEMM ----------------------------------
// C(128x128/CTA) = A(M x 4096) @ BT(N x 4096)^T, A,B each split hi/lo.
// 3 logical passes (AhBh + AhBl + AlBh) with shared fragment loads.
#define MMK       ZD               // 4096, both GEMMs
#define BKC       32               // K per stage (bf16)
#define NC        (MMK / BKC)      // 128 chunks
#define ROWB      80               // smem row stride bytes (conflict-free)
#define TILEB     (128 * ROWB)     // 10240 B per 128x32 tile
#define STAGEB    (4 * TILEB)      // Ah, Al, Bh, Bl
#define NSTAGE    3
#define MM_SMEM   (NSTAGE * STAGEB)  // 122880

__global__ __launch_bounds__(256) void mm_mma_kernel(
    const __nv_bfloat16* __restrict__ Ahi, const __nv_bfloat16* __restrict__ Alo,
    const __nv_bfloat16* __restrict__ Bhi, const __nv_bfloat16* __restrict__ Blo,
    const float* __restrict__ bias, int Nglob, int which)
{
    extern __shared__ char smem[];
    const uint32_t sb = smem_u32(smem);
    const int tid  = threadIdx.x;
    const int wid  = tid >> 5;
    const int lane = tid & 31;
    const int wm   = wid & 3;          // 4 m-blocks of 32
    const int wn   = wid >> 2;         // 2 n-blocks of 64

    const size_t mBase = (size_t)blockIdx.y * 128;
    const size_t nBase = (size_t)blockIdx.x * 128;

    const __nv_bfloat16* tp[4] = { Ahi, Alo, Bhi, Blo };
    const size_t         rb[4] = { mBase, mBase, nBase, nBase };

    auto issue = [&](int chunk, int stage) {
        const size_t kB = (size_t)chunk * BKC;
        const uint32_t stB = sb + stage * STAGEB;
        #pragma unroll
        for (int i = 0; i < 8; ++i) {
            int u    = tid + 256 * i;
            int tile = u >> 9;
            int idx  = u & 511;
            int row  = idx >> 2;
            int seg  = idx & 3;
            const __nv_bfloat16* src = tp[tile] + (rb[tile] + row) * MMK + kB + seg * 8;
            cp16(stB + tile * TILEB + row * ROWB + seg * 16, src);
        }
    };

    float acc[2][8][4];
    #pragma unroll
    for (int a = 0; a < 2; ++a)
        #pragma unroll
        for (int b = 0; b < 8; ++b)
            #pragma unroll
            for (int c = 0; c < 4; ++c) acc[a][b][c] = 0.0f;

    // fragment address lane math (identical to the passing R8 kernel)
    const int arow = wm * 32 + (lane & 7) + 8 * ((lane >> 3) & 1);
    const int brow = wn * 64 + (lane & 7) + 8 * (lane >> 4);
    const int acol_half = lane >> 4;
    const int bcol_half = (lane >> 3) & 1;

    // prologue: 2-deep prefetch into 3 stages
    issue(0, 0); cp_commit();
    issue(1, 1); cp_commit();
    cp_wait<1>();
    __syncthreads();

    for (int c = 0; c < NC; ++c) {
        if (c + 2 < NC) issue(c + 2, (c + 2) % NSTAGE);
        cp_commit();

        const uint32_t stB = sb + (c % NSTAGE) * STAGEB;
        #pragma unroll
        for (int ks = 0; ks < 2; ++ks) {
            const int k0 = 16 * ks;
            const uint32_t acolb = (uint32_t)(k0 + 8 * acol_half) * 2;
            const uint32_t bcolb = (uint32_t)(k0 + 8 * bcol_half) * 2;
            uint32_t Ah0[4], Ah1[4], Al0[4], Al1[4];
            ldsm_x4(Ah0, stB + 0 * TILEB + (uint32_t)arow * ROWB + acolb);
            ldsm_x4(Ah1, stB + 0 * TILEB + (uint32_t)(arow + 16) * ROWB + acolb);
            ldsm_x4(Al0, stB + 1 * TILEB + (uint32_t)arow * ROWB + acolb);
            ldsm_x4(Al1, stB + 1 * TILEB + (uint32_t)(arow + 16) * ROWB + acolb);
            uint32_t Bh[4][4], Bl[4][4];
            #pragma unroll
            for (int nb = 0; nb < 4; ++nb) {
                ldsm_x4(Bh[nb], stB + 2 * TILEB + (uint32_t)(brow + nb * 16) * ROWB + bcolb);
                ldsm_x4(Bl[nb], stB + 3 * TILEB + (uint32_t)(brow + nb * 16) * ROWB + bcolb);
            }
            #pragma unroll
            for (int nb = 0; nb < 4; ++nb) {
                // Ah x Bh
                mma16816(acc[0][2 * nb],     Ah0, Bh[nb][0], Bh[nb][1]);
                mma16816(acc[0][2 * nb + 1], Ah0, Bh[nb][2], Bh[nb][3]);
                mma16816(acc[1][2 * nb],     Ah1, Bh[nb][0], Bh[nb][1]);
                mma16816(acc[1][2 * nb + 1], Ah1, Bh[nb][2], Bh[nb][3]);
                // Ah x Bl
                mma16816(acc[0][2 * nb],     Ah0, Bl[nb][0], Bl[nb][1]);
                mma16816(acc[0][2 * nb + 1], Ah0, Bl[nb][2], Bl[nb][3]);
                mma16816(acc[1][2 * nb],     Ah1, Bl[nb][0], Bl[nb][1]);
                mma16816(acc[1][2 * nb + 1], Ah1, Bl[nb][2], Bl[nb][3]);
                // Al x Bh
                mma16816(acc[0][2 * nb],     Al0, Bh[nb][0], Bh[nb][1]);
                mma16816(acc[0][2 * nb + 1], Al0, Bh[nb][2], Bh[nb][3]);
                mma16816(acc[1][2 * nb],     Al1, Bh[nb][0], Bh[nb][1]);
                mma16816(acc[1][2 * nb + 1], Al1, Bh[nb][2], Bh[nb][3]);
            }
        }
        cp_wait<1>();
        __syncthreads();
    }

    // epilogue
    const int rrow = (lane >> 2);
    const int ccol = 2 * (lane & 3);
    #pragma unroll
    for (int mi = 0; mi < 2; ++mi) {
        const size_t r0 = mBase + wm * 32 + mi * 16 + rrow;
        #pragma unroll
        for (int n8 = 0; n8 < 8; ++n8) {
            const int col = (int)nBase + wn * 64 + n8 * 8 + ccol;
            const float bz0 = __ldg(&bias[col]);
            const float bz1 = __ldg(&bias[col + 1]);
            const float* f = acc[mi][n8];
            if (which == 0) {
                #pragma unroll
                for (int h = 0; h < 2; ++h) {
                    const size_t r = r0 + 8 * h;
                    float v0 = f[2 * h]     + bz0;
                    float v1 = f[2 * h + 1] + bz1;
                    __nv_bfloat16 h0 = __float2bfloat16(v0);
                    __nv_bfloat16 h1 = __float2bfloat16(v1);
                    __nv_bfloat16 l0 = __float2bfloat16(v0 - __bfloat162float(h0));
                    __nv_bfloat16 l1 = __float2bfloat16(v1 - __bfloat162float(h1));
                    uint32_t hp = ((uint32_t)__bfloat16_as_ushort(h1) << 16) |
                                  (uint32_t)__bfloat16_as_ushort(h0);
                    uint32_t lp = ((uint32_t)__bfloat16_as_ushort(l1) << 16) |
                                  (uint32_t)__bfloat16_as_ushort(l0);
                    *(uint32_t*)&g_Xhi[r * (size_t)Nglob + col] = hp;
                    *(uint32_t*)&g_Xlo[r * (size_t)Nglob + col] = lp;
                }
            } else {
                #pragma unroll
                for (int h = 0; h < 2; ++h) {
                    const size_t r = r0 + 8 * h;
                    float2 v = make_float2(f[2 * h] + bz0, f[2 * h + 1] + bz1);
                    *(float2*)&g_GI[r * (size_t)Nglob + col] = v;
                }
            }
        }
    }
}

// ---------------- persistent GRU scan ---------------------------------------
// 128 CTAs x 256 threads, all co-resident (128 < 148 SMs). Each warp owns one
// hidden unit j; W_hh rows live in registers. h ping-pongs via g_hT ([k][b]
// layout) with a sense-reversing software grid barrier per timestep.
__global__ __launch_bounds__(256) void gru_scan_kernel(const float* __restrict__ b_hh)
{
    __shared__ float sh[HID * BATCH];    // h_prev, [k][b]
    __shared__ unsigned s_sense;
    const int tid  = threadIdx.x;
    const int warp = tid >> 5;
    const int lane = tid & 31;
    const int j = blockIdx.x * 8 + warp;

    // weights -> registers (coalesced loads, once)
    float w0[32], w1[32], w2[32];
    {
        const float* W0 = g_WhhT + (size_t)j * HID;
        const float* W1 = g_WhhT + (size_t)(HID + j) * HID;
        const float* W2 = g_WhhT + (size_t)(2 * HID + j) * HID;
        #pragma unroll
        for (int it = 0; it < 32; ++it) {
            const int k = lane + 32 * it;
            w0[it] = W0[k]; w1[it] = W1[k]; w2[it] = W2[k];
        }
    }
    const float bh0 = b_hh[j];
    const float bh1 = b_hh[HID + j];
    const float bh2 = b_hh[2 * HID + j];

    if (tid == 0) s_sense = g_bar_flag;
    for (int i = tid; i < HID * BATCH; i += 256) sh[i] = 0.0f;   // h0 = 0
    __syncthreads();
    unsigned sense = s_sense;

    for (int t = 0; t < WIN; ++t) {
        // prefetch gi for this warp (lane b < 8)
        float pir = 0.f, piu = 0.f, pin = 0.f;
        if (lane < 8) {
            const size_t r = (size_t)lane * WIN + t;
            const float* gi = g_GI + r * G3;
            pir = gi[j];
            piu = gi[HID + j];
            pin = gi[2 * HID + j];
        }

        float a0[8], a1[8], a2[8];
        #pragma unroll
        for (int b = 0; b < 8; ++b) { a0[b] = 0.f; a1[b] = 0.f; a2[b] = 0.f; }

        #pragma unroll 8
        for (int it = 0; it < 32; ++it) {
            const int k = lane + 32 * it;
            const float4* hp = (const float4*)&sh[k * 8];
            const float4 hA = hp[0];
            const float4 hB = hp[1];
            const float wr = w0[it], wu = w1[it], wn = w2[it];
            a0[0]=fmaf(wr,hA.x,a0[0]); a1[0]=fmaf(wu,hA.x,a1[0]); a2[0]=fmaf(wn,hA.x,a2[0]);
            a0[1]=fmaf(wr,hA.y,a0[1]); a1[1]=fmaf(wu,hA.y,a1[1]); a2[1]=fmaf(wn,hA.y,a2[1]);
            a0[2]=fmaf(wr,hA.z,a0[2]); a1[2]=fmaf(wu,hA.z,a1[2]); a2[2]=fmaf(wn,hA.z,a2[2]);
            a0[3]=fmaf(wr,hA.w,a0[3]); a1[3]=fmaf(wu,hA.w,a1[3]); a2[3]=fmaf(wn,hA.w,a2[3]);
            a0[4]=fmaf(wr,hB.x,a0[4]); a1[4]=fmaf(wu,hB.x,a1[4]); a2[4]=fmaf(wn,hB.x,a2[4]);
            a0[5]=fmaf(wr,hB.y,a0[5]); a1[5]=fmaf(wu,hB.y,a1[5]); a2[5]=fmaf(wn,hB.y,a2[5]);
            a0[6]=fmaf(wr,hB.z,a0[6]); a1[6]=fmaf(wu,hB.z,a1[6]); a2[6]=fmaf(wn,hB.z,a2[6]);
            a0[7]=fmaf(wr,hB.w,a0[7]); a1[7]=fmaf(wu,hB.w,a1[7]); a2[7]=fmaf(wn,hB.w,a2[7]);
        }

        #pragma unroll
        for (int off = 16; off > 0; off >>= 1) {
            #pragma unroll
            for (int b = 0; b < 8; ++b) {
                a0[b] += __shfl_xor_sync(0xffffffffu, a0[b], off);
                a1[b] += __shfl_xor_sync(0xffffffffu, a1[b], off);
                a2[b] += __shfl_xor_sync(0xffffffffu, a2[b], off);
            }
        }

        if (lane < 8) {
            float hr = 0.f, hu = 0.f, hn = 0.f;
            #pragma unroll
            for (int b = 0; b < 8; ++b)
                if (b == lane) { hr = a0[b]; hu = a1[b]; hn = a2[b]; }
            hr += bh0; hu += bh1; hn += bh2;
            const float rg = 1.0f / (1.0f + expf(-(pir + hr)));
            const float ug = 1.0f / (1.0f + expf(-(piu + hu)));
            const float ng = tanhf(fmaf(rg, hn, pin));
            const float hp = sh[j * 8 + lane];
            const float hnew = (1.0f - ug) * ng + ug * hp;
            g_hT[t & 1][j * 8 + lane] = hnew;
            g_H[((size_t)lane * WIN + t) * HID + j] = hnew;
            __threadfence();
        }
        __syncthreads();

        // grid barrier (sense-reversing)
        if (tid == 0) {
            const unsigned old = atomicAdd(&g_bar_ctr, 1u);
            if (old == NCTA_SCAN - 1) {
                g_bar_ctr = 0;
                __threadfence();
                g_bar_flag = sense ^ 1u;
            }
            while (g_bar_flag == sense) { __nanosleep(64); }
        }
        __syncthreads();
        __threadfence();
        sense ^= 1u;

        // reload h for next step
        if (t + 1 < WIN) {
            const float4* src = (const float4*)g_hT[t & 1];
            float4* dst = (float4*)sh;
            #pragma unroll
            for (int i = tid; i < HID * BATCH / 4; i += 256) dst[i] = src[i];
            __syncthreads();
        }
    }
}

// ---------------- dense + heads (unchanged) --------------------------------
__global__ __launch_bounds__(128) void dense_kernel(
    const float* __restrict__ Wd, const float* __restrict__ bd)
{
    __shared__ float sh[8 * HID];
    const int r0 = blockIdx.x * 8;
    for (int i = threadIdx.x; i < 8 * HID; i += 128)
        sh[i] = g_H[(size_t)r0 * HID + i];
    __syncthreads();

    const int c = threadIdx.x;
    if (c < DEN) {
        float acc[8];
        #pragma unroll
        for (int i = 0; i < 8; ++i) acc[i] = bd[c];
        #pragma unroll 4
        for (int k = 0; k < HID; ++k) {
            const float w = Wd[k * DEN + c];
            #pragma unroll
            for (int i = 0; i < 8; ++i)
                acc[i] = fmaf(sh[i * HID + k], w, acc[i]);
        }
        #pragma unroll
        for (int i = 0; i < 8; ++i)
            g_D[(size_t)(r0 + i) * DEN + c] = acc[i];
    }
}

__global__ __launch_bounds__(128) void heads_kernel(
    const float* __restrict__ W_mu, const float* __restrict__ b_mu,
    const float* __restrict__ W_sg, const float* __restrict__ b_sg,
    const float* __restrict__ noise, float* __restrict__ out)
{
    __shared__ float sh[16 * DEN];
    const int r0 = blockIdx.x * 16;
    for (int i = threadIdx.x; i < 16 * DEN; i += 128)
        sh[i] = g_D[(size_t)r0 * DEN + i];
    __syncthreads();

    const int c = threadIdx.x;
    if (c < OUT_D) {
        float am[16], as[16];
        #pragma unroll
        for (int i = 0; i < 16; ++i) { am[i] = b_mu[c]; as[i] = b_sg[c]; }
        #pragma unroll 2
        for (int k = 0; k < DEN; ++k) {
            const float wm = W_mu[k * OUT_D + c];
            const float ws = W_sg[k * OUT_D + c];
            #pragma unroll
            for (int i = 0; i < 16; ++i) {
                const float d = sh[i * DEN + k];
                am[i] = fmaf(d, wm, am[i]);
                as[i] = fmaf(d, ws, as[i]);
            }
        }
        #pragma unroll
        for (int i = 0; i < 16; ++i) {
            const size_t r = (size_t)(r0 + i);
            const float x = as[i];
            const float sp = fmaxf(x, 0.0f) + log1pf(expf(-fabsf(x)));
            out[r * OUT_D + c] = fmaf(sp, noise[r * OUT_D + c], am[i]);
        }
    }
}

// ---------------------------------------------------------------------------
extern "C" void kernel_launch(void* const* d_in, const int* in_sizes, int n_in,
                              void* d_out, int out_size)
{
    const float* z        = (const float*)d_in[0];
    const float* noise    = (const float*)d_in[1];
    const float* W_lgssm  = (const float*)d_in[2];
    const float* b_lgssm  = (const float*)d_in[3];
    const float* W_ih     = (const float*)d_in[4];
    const float* b_ih     = (const float*)d_in[5];
    const float* W_hh     = (const float*)d_in[6];
    const float* b_hh     = (const float*)d_in[7];
    const float* W_dense  = (const float*)d_in[8];
    const float* b_dense  = (const float*)d_in[9];
    const float* W_mu     = (const float*)d_in[10];
    const float* b_mu     = (const float*)d_in[11];
    const float* W_sigma  = (const float*)d_in[12];
    const float* b_sigma  = (const float*)d_in[13];
    float* out = (float*)d_out;

    static int attr_done = 0;
    if (!attr_done) {
        cudaFuncSetAttribute(mm_mma_kernel,
                             cudaFuncAttributeMaxDynamicSharedMemorySize, MM_SMEM);
        attr_done = 1;
    }

    __nv_bfloat16 *p_zhi, *p_zlo, *p_Wlg_hi, *p_Wlg_lo, *p_Wih_hi, *p_Wih_lo;
    __nv_bfloat16 *p_Xhi, *p_Xlo;
    cudaGetSymbolAddress((void**)&p_zhi,    g_zhi);
    cudaGetSymbolAddress((void**)&p_zlo,    g_zlo);
    cudaGetSymbolAddress((void**)&p_Wlg_hi, g_WlgT_hi);
    cudaGetSymbolAddress((void**)&p_Wlg_lo, g_WlgT_lo);
    cudaGetSymbolAddress((void**)&p_Wih_hi, g_WihT_hi);
    cudaGetSymbolAddress((void**)&p_Wih_lo, g_WihT_lo);
    cudaGetSymbolAddress((void**)&p_Xhi,    g_Xhi);
    cudaGetSymbolAddress((void**)&p_Xlo,    g_Xlo);

    // conversions
    transpose_whh_kernel<<<dim3(G3 / 32, HID / 32), dim3(32, 8)>>>(W_hh);
    conv_split_kernel<<<2048, 256>>>(z, p_zhi, p_zlo, ROWS * ZD);
    transpose_split_kernel<<<dim3(ZD / 32, ZD / 32), dim3(32, 8)>>>(
        W_lgssm, p_Wlg_hi, p_Wlg_lo, ZD, ZD);
    transpose_split_kernel<<<dim3(G3 / 32, ZD / 32), dim3(32, 8)>>>(
        W_ih, p_Wih_hi, p_Wih_lo, ZD, G3);

    // GEMM1: X = z @ W_lgssm + b_lgssm -> bf16 hi/lo split
    mm_mma_kernel<<<dim3(ZD / 128, ROWS / 128), 256, MM_SMEM>>>(
        p_zhi, p_zlo, p_Wlg_hi, p_Wlg_lo, b_lgssm, ZD, 0);
    // GEMM2: GI = X @ W_ih + b_ih -> fp32
    mm_mma_kernel<<<dim3(G3 / 128, ROWS / 128), 256, MM_SMEM>>>(
        p_Xhi, p_Xlo, p_Wih_hi, p_Wih_lo, b_ih, G3, 1);

    // persistent GRU scan (single kernel, software grid barrier)
    gru_scan_kernel<<<NCTA_SCAN, 256>>>(b_hh);

    // deferred output path
    dense_kernel<<<ROWS / 8, 128>>>(W_dense, b_dense);
    heads_kernel<<<ROWS / 16, 128>>>(W_mu, b_mu, W_sigma, b_sigma, noise, out);
}

// round 10
// speedup vs baseline: 1.8313x; 1.0573x over previous
#include <cuda_runtime.h>
#include <cuda_bf16.h>
#include <math.h>
#include <stdint.h>

// Problem dims
#define ZD   4096
#define HID  1024
#define DEN  100
#define OUT_D 100
#define BATCH 8
#define WIN  512
#define ROWS (BATCH * WIN)      // 4096
#define G3   (3 * HID)          // 3072

// ---------------- scratch (__device__ globals; no allocation allowed) ------
__device__ __nv_bfloat16 g_zhi [ (size_t)ROWS * ZD ];    // z split
__device__ __nv_bfloat16 g_zlo [ (size_t)ROWS * ZD ];
__device__ __nv_bfloat16 g_Wlg_hi[ (size_t)ZD * ZD ];    // W_lgssm split (as stored, i x m)
__device__ __nv_bfloat16 g_Wlg_lo[ (size_t)ZD * ZD ];
__device__ __nv_bfloat16 g_WihT_hi[ (size_t)G3 * ZD ];   // W_ih transposed (o x m)
__device__ __nv_bfloat16 g_WihT_lo[ (size_t)G3 * ZD ];
__device__ __nv_bfloat16 g_WcT_hi[ (size_t)G3 * ZD ];    // W_combT = (Wlg@Wih)^T  (o x i)
__device__ __nv_bfloat16 g_WcT_lo[ (size_t)G3 * ZD ];
__device__ float g_GI  [ (size_t)ROWS * G3 ];            // z@W_comb + b_comb (fp32)
__device__ float g_bcomb[G3];
__device__ float g_zb  [ZD];                             // stays zero (zero-init)
__device__ float g_WhhT[ (size_t)G3 * HID ];
__device__ float g_H   [ (size_t)ROWS * HID ];
__device__ float g_D   [ (size_t)ROWS * DEN ];
__device__ float g_hT  [2][HID * BATCH];                 // ping-pong h, [k][b]

// grid-barrier state for the persistent scan
#define NCTA_SCAN 128
__device__ unsigned g_bar_ctr = 0;
__device__ volatile unsigned g_bar_flag = 0;

// ---------------- helpers ---------------------------------------------------
__device__ __forceinline__ uint32_t smem_u32(const void* p) {
    uint32_t a;
    asm("{ .reg .u64 t; cvta.to.shared.u64 t, %1; cvt.u32.u64 %0, t; }"
        : "=r"(a) : "l"(p));
    return a;
}
__device__ __forceinline__ void cp16(uint32_t dst, const void* src) {
    asm volatile(
        "{ .reg .u64 g; cvta.to.global.u64 g, %1; "
        "cp.async.cg.shared.global [%0], [g], 16; }"
        :: "r"(dst), "l"(src) : "memory");
}
__device__ __forceinline__ void cp_commit() {
    asm volatile("cp.async.commit_group;" ::: "memory");
}
template <int N>
__device__ __forceinline__ void cp_wait() {
    asm volatile("cp.async.wait_group %0;" :: "n"(N) : "memory");
}
__device__ __forceinline__ void ldsm_x4(uint32_t* r, uint32_t addr) {
    asm volatile("ldmatrix.sync.aligned.m8n8.x4.shared.b16 {%0,%1,%2,%3}, [%4];"
        : "=r"(r[0]), "=r"(r[1]), "=r"(r[2]), "=r"(r[3]) : "r"(addr));
}
__device__ __forceinline__ void mma16816(float* d, const uint32_t* a,
                                         uint32_t b0, uint32_t b1) {
    asm volatile(
        "mma.sync.aligned.m16n8k16.row.col.f32.bf16.bf16.f32 "
        "{%0,%1,%2,%3}, {%4,%5,%6,%7}, {%8,%9}, {%0,%1,%2,%3};"
        : "+f"(d[0]), "+f"(d[1]), "+f"(d[2]), "+f"(d[3])
        : "r"(a[0]), "r"(a[1]), "r"(a[2]), "r"(a[3]), "r"(b0), "r"(b1));
}

// ---------------- conversion kernels ---------------------------------------
__global__ __launch_bounds__(256) void conv_split_kernel(
    const float* __restrict__ src, __nv_bfloat16* __restrict__ hi,
    __nv_bfloat16* __restrict__ lo, int n)
{
    for (int i = blockIdx.x * 256 + threadIdx.x; i < n; i += gridDim.x * 256) {
        float x = src[i];
        __nv_bfloat16 h = __float2bfloat16(x);
        hi[i] = h;
        lo[i] = __float2bfloat16(x - __bfloat162float(h));
    }
}

// transpose (K x N fp32) -> (N x K bf16 hi/lo)
__global__ __launch_bounds__(256) void transpose_split_kernel(
    const float* __restrict__ W, __nv_bfloat16* __restrict__ Thi,
    __nv_bfloat16* __restrict__ Tlo, int K, int N)
{
    __shared__ float tile[32][33];
    int tx = threadIdx.x, ty = threadIdx.y;
    int x = blockIdx.x * 32 + tx;
    int y0 = blockIdx.y * 32;
    #pragma unroll
    for (int j = ty; j < 32; j += 8)
        tile[j][tx] = W[(size_t)(y0 + j) * N + x];
    __syncthreads();
    int k = blockIdx.y * 32 + tx;
    int n0 = blockIdx.x * 32;
    #pragma unroll
    for (int j = ty; j < 32; j += 8) {
        float v = tile[tx][j];
        __nv_bfloat16 h = __float2bfloat16(v);
        size_t o = (size_t)(n0 + j) * K + k;
        Thi[o] = h;
        Tlo[o] = __float2bfloat16(v - __bfloat162float(h));
    }
}

__global__ void transpose_whh_kernel(const float* __restrict__ W) {
    __shared__ float tile[32][33];
    int x = blockIdx.x * 32 + threadIdx.x;
    int y0 = blockIdx.y * 32;
    #pragma unroll
    for (int j = threadIdx.y; j < 32; j += 8)
        tile[j][threadIdx.x] = W[(size_t)(y0 + j) * G3 + x];
    __syncthreads();
    int xt  = blockIdx.y * 32 + threadIdx.x;
    int yt0 = blockIdx.x * 32;
    #pragma unroll
    for (int j = threadIdx.y; j < 32; j += 8)
        g_WhhT[(size_t)(yt0 + j) * HID + xt] = tile[threadIdx.x][j];
}

// b_comb[o] = b_ih[o] + sum_m b_lgssm[m] * W_ih[m][o]
__global__ __launch_bounds__(256) void bcomb_kernel(
    const float* __restrict__ W_ih, const float* __restrict__ b_lg,
    const float* __restrict__ b_ih)
{
    const int o = blockIdx.x * 256 + threadIdx.x;
    float acc = b_ih[o];
    for (int m = 0; m < ZD; ++m)
        acc = fmaf(b_lg[m], W_ih[(size_t)m * G3 + o], acc);
    g_bcomb[o] = acc;
}

// ---------------- split-bf16 mma.sync GEMM (128x256 CTA tile, 512 thr) ------
// C[r][c] = sum_k A[r][k] * BT[c][k], A/B each split hi/lo, 3 passes
// (AhBh + AhBl + AlBh) into one fp32 accumulator. K = 4096 always.
// which==0: epilogue re-splits to (Chi, Clo) bf16 (+bias).
// which==1: epilogue writes fp32 to g_GI (+bias).
#define MMK       ZD               // 4096 for both GEMMs
#define BKC       32               // K per stage (bf16)
#define NC        (MMK / BKC)      // 128 chunks
#define ROWB      80               // smem row stride bytes (conflict-free)
#define A_TILEB   (128 * ROWB)     // 10240
#define B_TILEB   (256 * ROWB)     // 20480
#define STAGEB    (2 * A_TILEB + 2 * B_TILEB)  // 61440: Ah, Al, Bh, Bl
#define NSTAGE    2
#define MM_SMEM   (NSTAGE * STAGEB)            // 122880

__global__ __launch_bounds__(512) void mm_mma_kernel(
    const __nv_bfloat16* __restrict__ Ahi, const __nv_bfloat16* __restrict__ Alo,
    const __nv_bfloat16* __restrict__ Bhi, const __nv_bfloat16* __restrict__ Blo,
    const float* __restrict__ bias,
    __nv_bfloat16* __restrict__ Chi, __nv_bfloat16* __restrict__ Clo,
    int Nglob, int which)
{
    extern __shared__ char smem[];
    const uint32_t sb = smem_u32(smem);
    const int tid  = threadIdx.x;
    const int wid  = tid >> 5;
    const int lane = tid & 31;
    const int wm   = wid & 3;          // 4 m-blocks of 32  -> 128
    const int wn   = wid >> 2;         // 4 n-blocks of 64  -> 256

    const size_t mBase = (size_t)blockIdx.y * 128;
    const size_t nBase = (size_t)blockIdx.x * 256;

    const __nv_bfloat16* tp[4] = { Ahi, Alo, Bhi, Blo };
    const size_t rb[4]  = { mBase, mBase, nBase, nBase };
    const uint32_t toff[4] = { 0, A_TILEB, 2 * A_TILEB, 2 * A_TILEB + B_TILEB };

    // one stage = 3072 cp16 (A: 2x128 rows, B: 2x256 rows, 4 segs each)
    auto issue = [&](int chunk, int stage) {
        const size_t kB = (size_t)chunk * BKC;
        const uint32_t stB = sb + stage * STAGEB;
        #pragma unroll
        for (int i = 0; i < 6; ++i) {
            const int u   = tid + 512 * i;
            const int r   = u >> 2;
            const int seg = u & 3;
            int tile, lrow;
            if (r < 128)      { tile = 0; lrow = r; }
            else if (r < 256) { tile = 1; lrow = r - 128; }
            else if (r < 512) { tile = 2; lrow = r - 256; }
            else              { tile = 3; lrow = r - 512; }
            const __nv_bfloat16* src =
                tp[tile] + (rb[tile] + lrow) * MMK + kB + seg * 8;
            cp16(stB + toff[tile] + lrow * ROWB + seg * 16, src);
        }
    };

    float acc[2][8][4];
    #pragma unroll
    for (int a = 0; a < 2; ++a)
        #pragma unroll
        for (int b = 0; b < 8; ++b)
            #pragma unroll
            for (int c = 0; c < 4; ++c) acc[a][b][c] = 0.0f;

    const int arow = wm * 32 + (lane & 7) + 8 * ((lane >> 3) & 1);
    const int brow = wn * 64 + (lane & 7) + 8 * (lane >> 4);
    const int acol_half = lane >> 4;
    const int bcol_half = (lane >> 3) & 1;

    issue(0, 0); cp_commit();
    issue(1, 1); cp_commit();
    cp_wait<1>();
    __syncthreads();

    for (int c = 0; c < NC; ++c) {
        const int s = c & 1;
        const uint32_t stB = sb + s * STAGEB;
        const uint32_t AhB = stB;
        const uint32_t AlB = stB + A_TILEB;
        const uint32_t BhB = stB + 2 * A_TILEB;
        const uint32_t BlB = stB + 2 * A_TILEB + B_TILEB;

        #pragma unroll
        for (int ks = 0; ks < 2; ++ks) {
            const uint32_t acolb = (uint32_t)(16 * ks + 8 * acol_half) * 2;
            const uint32_t bcolb = (uint32_t)(16 * ks + 8 * bcol_half) * 2;
            uint32_t Ah0[4], Ah1[4], Al0[4], Al1[4];
            ldsm_x4(Ah0, AhB + (uint32_t)arow * ROWB + acolb);
            ldsm_x4(Ah1, AhB + (uint32_t)(arow + 16) * ROWB + acolb);
            ldsm_x4(Al0, AlB + (uint32_t)arow * ROWB + acolb);
            ldsm_x4(Al1, AlB + (uint32_t)(arow + 16) * ROWB + acolb);
            #pragma unroll
            for (int nb = 0; nb < 4; ++nb) {
                const uint32_t brb = (uint32_t)(brow + nb * 16) * ROWB + bcolb;
                uint32_t bh[4], bl[4];
                ldsm_x4(bh, BhB + brb);
                ldsm_x4(bl, BlB + brb);
                // Ah x Bh
                mma16816(acc[0][2 * nb],     Ah0, bh[0], bh[1]);
                mma16816(acc[0][2 * nb + 1], Ah0, bh[2], bh[3]);
                mma16816(acc[1][2 * nb],     Ah1, bh[0], bh[1]);
                mma16816(acc[1][2 * nb + 1], Ah1, bh[2], bh[3]);
                // Ah x Bl
                mma16816(acc[0][2 * nb],     Ah0, bl[0], bl[1]);
                mma16816(acc[0][2 * nb + 1], Ah0, bl[2], bl[3]);
                mma16816(acc[1][2 * nb],     Ah1, bl[0], bl[1]);
                mma16816(acc[1][2 * nb + 1], Ah1, bl[2], bl[3]);
                // Al x Bh
                mma16816(acc[0][2 * nb],     Al0, bh[0], bh[1]);
                mma16816(acc[0][2 * nb + 1], Al0, bh[2], bh[3]);
                mma16816(acc[1][2 * nb],     Al1, bh[0], bh[1]);
                mma16816(acc[1][2 * nb + 1], Al1, bh[2], bh[3]);
            }
        }
        __syncthreads();                       // all warps done reading stage s
        if (c + 2 < NC) issue(c + 2, s);
        cp_commit();                           // empty group if nothing issued
        cp_wait<1>();                          // chunk c+1 resident
        __syncthreads();
    }

    // epilogue
    const int rrow = (lane >> 2);
    const int ccol = 2 * (lane & 3);
    #pragma unroll
    for (int mi = 0; mi < 2; ++mi) {
        const size_t r0 = mBase + wm * 32 + mi * 16 + rrow;
        #pragma unroll
        for (int n8 = 0; n8 < 8; ++n8) {
            const int col = (int)nBase + wn * 64 + n8 * 8 + ccol;
            const float bz0 = __ldg(&bias[col]);
            const float bz1 = __ldg(&bias[col + 1]);
            const float* f = acc[mi][n8];
            if (which == 0) {
                #pragma unroll
                for (int h = 0; h < 2; ++h) {
                    const size_t r = r0 + 8 * h;
                    float v0 = f[2 * h]     + bz0;
                    float v1 = f[2 * h + 1] + bz1;
                    __nv_bfloat16 h0 = __float2bfloat16(v0);
                    __nv_bfloat16 h1 = __float2bfloat16(v1);
                    __nv_bfloat16 l0 = __float2bfloat16(v0 - __bfloat162float(h0));
                    __nv_bfloat16 l1 = __float2bfloat16(v1 - __bfloat162float(h1));
                    uint32_t hp = ((uint32_t)__bfloat16_as_ushort(h1) << 16) |
                                  (uint32_t)__bfloat16_as_ushort(h0);
                    uint32_t lp = ((uint32_t)__bfloat16_as_ushort(l1) << 16) |
                                  (uint32_t)__bfloat16_as_ushort(l0);
                    *(uint32_t*)&Chi[r * (size_t)Nglob + col] = hp;
                    *(uint32_t*)&Clo[r * (size_t)Nglob + col] = lp;
                }
            } else {
                #pragma unroll
                for (int h = 0; h < 2; ++h) {
                    const size_t r = r0 + 8 * h;
                    float2 v = make_float2(f[2 * h] + bz0, f[2 * h + 1] + bz1);
                    *(float2*)&g_GI[r * (size_t)Nglob + col] = v;
                }
            }
        }
    }
}

// ---------------- persistent GRU scan ---------------------------------------
__global__ __launch_bounds__(256) void gru_scan_kernel(const float* __restrict__ b_hh)
{
    __shared__ float sh[HID * BATCH];    // h_prev, [k][b]
    __shared__ unsigned s_sense;
    const int tid  = threadIdx.x;
    const int warp = tid >> 5;
    const int lane = tid & 31;
    const int j = blockIdx.x * 8 + warp;

    // weights -> registers (coalesced loads, once)
    float w0[32], w1[32], w2[32];
    {
        const float* W0 = g_WhhT + (size_t)j * HID;
        const float* W1 = g_WhhT + (size_t)(HID + j) * HID;
        const float* W2 = g_WhhT + (size_t)(2 * HID + j) * HID;
        #pragma unroll
        for (int it = 0; it < 32; ++it) {
            const int k = lane + 32 * it;
            w0[it] = W0[k]; w1[it] = W1[k]; w2[it] = W2[k];
        }
    }
    const float bh0 = b_hh[j];
    const float bh1 = b_hh[HID + j];
    const float bh2 = b_hh[2 * HID + j];

    if (tid == 0) s_sense = g_bar_flag;
    for (int i = tid; i < HID * BATCH; i += 256) sh[i] = 0.0f;   // h0 = 0
    __syncthreads();
    unsigned sense = s_sense;

    for (int t = 0; t < WIN; ++t) {
        float pir = 0.f, piu = 0.f, pin = 0.f;
        if (lane < 8) {
            const size_t r = (size_t)lane * WIN + t;
            const float* gi = g_GI + r * G3;
            pir = gi[j];
            piu = gi[HID + j];
            pin = gi[2 * HID + j];
        }

        float a0[8], a1[8], a2[8];
        #pragma unroll
        for (int b = 0; b < 8; ++b) { a0[b] = 0.f; a1[b] = 0.f; a2[b] = 0.f; }

        #pragma unroll 8
        for (int it = 0; it < 32; ++it) {
            const int k = lane + 32 * it;
            const float4* hp = (const float4*)&sh[k * 8];
            const float4 hA = hp[0];
            const float4 hB = hp[1];
            const float wr = w0[it], wu = w1[it], wn = w2[it];
            a0[0]=fmaf(wr,hA.x,a0[0]); a1[0]=fmaf(wu,hA.x,a1[0]); a2[0]=fmaf(wn,hA.x,a2[0]);
            a0[1]=fmaf(wr,hA.y,a0[1]); a1[1]=fmaf(wu,hA.y,a1[1]); a2[1]=fmaf(wn,hA.y,a2[1]);
            a0[2]=fmaf(wr,hA.z,a0[2]); a1[2]=fmaf(wu,hA.z,a1[2]); a2[2]=fmaf(wn,hA.z,a2[2]);
            a0[3]=fmaf(wr,hA.w,a0[3]); a1[3]=fmaf(wu,hA.w,a1[3]); a2[3]=fmaf(wn,hA.w,a2[3]);
            a0[4]=fmaf(wr,hB.x,a0[4]); a1[4]=fmaf(wu,hB.x,a1[4]); a2[4]=fmaf(wn,hB.x,a2[4]);
            a0[5]=fmaf(wr,hB.y,a0[5]); a1[5]=fmaf(wu,hB.y,a1[5]); a2[5]=fmaf(wn,hB.y,a2[5]);
            a0[6]=fmaf(wr,hB.z,a0[6]); a1[6]=fmaf(wu,hB.z,a1[6]); a2[6]=fmaf(wn,hB.z,a2[6]);
            a0[7]=fmaf(wr,hB.w,a0[7]); a1[7]=fmaf(wu,hB.w,a1[7]); a2[7]=fmaf(wn,hB.w,a2[7]);
        }

        #pragma unroll
        for (int off = 16; off > 0; off >>= 1) {
            #pragma unroll
            for (int b = 0; b < 8; ++b) {
                a0[b] += __shfl_xor_sync(0xffffffffu, a0[b], off);
                a1[b] += __shfl_xor_sync(0xffffffffu, a1[b], off);
                a2[b] += __shfl_xor_sync(0xffffffffu, a2[b], off);
            }
        }

        if (lane < 8) {
            float hr = 0.f, hu = 0.f, hn = 0.f;
            #pragma unroll
            for (int b = 0; b < 8; ++b)
                if (b == lane) { hr = a0[b]; hu = a1[b]; hn = a2[b]; }
            hr += bh0; hu += bh1; hn += bh2;
            const float rg = 1.0f / (1.0f + expf(-(pir + hr)));
            const float ug = 1.0f / (1.0f + expf(-(piu + hu)));
            const float ng = tanhf(fmaf(rg, hn, pin));
            const float hp = sh[j * 8 + lane];
            const float hnew = (1.0f - ug) * ng + ug * hp;
            g_hT[t & 1][j * 8 + lane] = hnew;
            g_H[((size_t)lane * WIN + t) * HID + j] = hnew;
        }
        __syncthreads();

        // grid barrier (sense-reversing); single release/acquire fence per CTA
        if (tid == 0) {
            __threadfence();                       // release CTA's h stores
            const unsigned old = atomicAdd(&g_bar_ctr, 1u);
            if (old == NCTA_SCAN - 1) {
                g_bar_ctr = 0;
                __threadfence();
                g_bar_flag = sense ^ 1u;
            }
            while (g_bar_flag == sense) { __nanosleep(32); }
            __threadfence();                       // acquire
        }
        __syncthreads();
        sense ^= 1u;

        // reload h for next step
        if (t + 1 < WIN) {
            const float4* src = (const float4*)g_hT[t & 1];
            float4* dst = (float4*)sh;
            #pragma unroll
            for (int i = tid; i < HID * BATCH / 4; i += 256) dst[i] = src[i];
            __syncthreads();
        }
    }
}

// ---------------- dense + heads (unchanged) --------------------------------
__global__ __launch_bounds__(128) void dense_kernel(
    const float* __restrict__ Wd, const float* __restrict__ bd)
{
    __shared__ float sh[8 * HID];
    const int r0 = blockIdx.x * 8;
    for (int i = threadIdx.x; i < 8 * HID; i += 128)
        sh[i] = g_H[(size_t)r0 * HID + i];
    __syncthreads();

    const int c = threadIdx.x;
    if (c < DEN) {
        float acc[8];
        #pragma unroll
        for (int i = 0; i < 8; ++i) acc[i] = bd[c];
        #pragma unroll 4
        for (int k = 0; k < HID; ++k) {
            const float w = Wd[k * DEN + c];
            #pragma unroll
            for (int i = 0; i < 8; ++i)
                acc[i] = fmaf(sh[i * HID + k], w, acc[i]);
        }
        #pragma unroll
        for (int i = 0; i < 8; ++i)
            g_D[(size_t)(r0 + i) * DEN + c] = acc[i];
    }
}

__global__ __launch_bounds__(128) void heads_kernel(
    const float* __restrict__ W_mu, const float* __restrict__ b_mu,
    const float* __restrict__ W_sg, const float* __restrict__ b_sg,
    const float* __restrict__ noise, float* __restrict__ out)
{
    __shared__ float sh[16 * DEN];
    const int r0 = blockIdx.x * 16;
    for (int i = threadIdx.x; i < 16 * DEN; i += 128)
        sh[i] = g_D[(size_t)r0 * DEN + i];
    __syncthreads();

    const int c = threadIdx.x;
    if (c < OUT_D) {
        float am[16], as[16];
        #pragma unroll
        for (int i = 0; i < 16; ++i) { am[i] = b_mu[c]; as[i] = b_sg[c]; }
        #pragma unroll 2
        for (int k = 0; k < DEN; ++k) {
            const float wm = W_mu[k * OUT_D + c];
            const float ws = W_sg[k * OUT_D + c];
            #pragma unroll
            for (int i = 0; i < 16; ++i) {
                const float d = sh[i * DEN + k];
                am[i] = fmaf(d, wm, am[i]);
                as[i] = fmaf(d, ws, as[i]);
            }
        }
        #pragma unroll
        for (int i = 0; i < 16; ++i) {
            const size_t r = (size_t)(r0 + i);
            const float x = as[i];
            const float sp = fmaxf(x, 0.0f) + log1pf(expf(-fabsf(x)));
            out[r * OUT_D + c] = fmaf(sp, noise[r * OUT_D + c], am[i]);
        }
    }
}

// ---------------------------------------------------------------------------
extern "C" void kernel_launch(void* const* d_in, const int* in_sizes, int n_in,
                              void* d_out, int out_size)
{
    const float* z        = (const float*)d_in[0];
    const float* noise    = (const float*)d_in[1];
    const float* W_lgssm  = (const float*)d_in[2];
    const float* b_lgssm  = (const float*)d_in[3];
    const float* W_ih     = (const float*)d_in[4];
    const float* b_ih     = (const float*)d_in[5];
    const float* W_hh     = (const float*)d_in[6];
    const float* b_hh     = (const float*)d_in[7];
    const float* W_dense  = (const float*)d_in[8];
    const float* b_dense  = (const float*)d_in[9];
    const float* W_mu     = (const float*)d_in[10];
    const float* b_mu     = (const float*)d_in[11];
    const float* W_sigma  = (const float*)d_in[12];
    const float* b_sigma  = (const float*)d_in[13];
    float* out = (float*)d_out;

    static int attr_done = 0;
    if (!attr_done) {
        cudaFuncSetAttribute(mm_mma_kernel,
                             cudaFuncAttributeMaxDynamicSharedMemorySize, MM_SMEM);
        attr_done = 1;
    }

    __nv_bfloat16 *p_zhi, *p_zlo, *p_Wlg_hi, *p_Wlg_lo, *p_Wih_hi, *p_Wih_lo;
    __nv_bfloat16 *p_WcT_hi, *p_WcT_lo;
    float *p_bcomb, *p_zb;
    cudaGetSymbolAddress((void**)&p_zhi,    g_zhi);
    cudaGetSymbolAddress((void**)&p_zlo,    g_zlo);
    cudaGetSymbolAddress((void**)&p_Wlg_hi, g_Wlg_hi);
    cudaGetSymbolAddress((void**)&p_Wlg_lo, g_Wlg_lo);
    cudaGetSymbolAddress((void**)&p_Wih_hi, g_WihT_hi);
    cudaGetSymbolAddress((void**)&p_Wih_lo, g_WihT_lo);
    cudaGetSymbolAddress((void**)&p_WcT_hi, g_WcT_hi);
    cudaGetSymbolAddress((void**)&p_WcT_lo, g_WcT_lo);
    cudaGetSymbolAddress((void**)&p_bcomb,  g_bcomb);
    cudaGetSymbolAddress((void**)&p_zb,     g_zb);

    // conversions + bias fold
    transpose_whh_kernel<<<dim3(G3 / 32, HID / 32), dim3(32, 8)>>>(W_hh);
    conv_split_kernel<<<2048, 256>>>(z, p_zhi, p_zlo, ROWS * ZD);
    conv_split_kernel<<<2048, 256>>>(W_lgssm, p_Wlg_hi, p_Wlg_lo, ZD * ZD);
    transpose_split_kernel<<<dim3(G3 / 32, ZD / 32), dim3(32, 8)>>>(
        W_ih, p_Wih_hi, p_Wih_lo, ZD, G3);
    bcomb_kernel<<<G3 / 256, 256>>>(W_ih, b_lgssm, b_ih);

    // fold GEMM: W_combT[o][i] = sum_m W_ihT[o][m] * W_lgssm[i][m]
    //   M = 3072 (o), N = 4096 (i), K = 4096 -> bf16 hi/lo split output
    mm_mma_kernel<<<dim3(ZD / 256, G3 / 128), 512, MM_SMEM>>>(
        p_Wih_hi, p_Wih_lo, p_Wlg_hi, p_Wlg_lo, p_zb, p_WcT_hi, p_WcT_lo, ZD, 0);

    // data GEMM: GI[r][o] = sum_i z[r][i] * W_combT[o][i] + b_comb[o]
    //   M = 4096 (r), N = 3072 (o), K = 4096 -> fp32
    mm_mma_kernel<<<dim3(G3 / 256, ROWS / 128), 512, MM_SMEM>>>(
        p_zhi, p_zlo, p_WcT_hi, p_WcT_lo, p_bcomb, nullptr, nullptr, G3, 1);

    // persistent GRU scan (single kernel, software grid barrier)
    gru_scan_kernel<<<NCTA_SCAN, 256>>>(b_hh);

    // deferred output path
    dense_kernel<<<ROWS / 8, 128>>>(W_dense, b_dense);
    heads_kernel<<<ROWS / 16, 128>>>(W_mu, b_mu, W_sigma, b_sigma, noise, out);
}

// round 11
// speedup vs baseline: 2.0244x; 1.1054x over previous
#include <cuda_runtime.h>
#include <cuda_bf16.h>
#include <math.h>
#include <stdint.h>

// Problem dims
#define ZD   4096
#define HID  1024
#define DEN  100
#define OUT_D 100
#define BATCH 8
#define WIN  512
#define ROWS (BATCH * WIN)      // 4096
#define G3   (3 * HID)          // 3072

// ---------------- scratch (__device__ globals; no allocation allowed) ------
__device__ __nv_bfloat16 g_zhi [ (size_t)ROWS * ZD ];    // z split
__device__ __nv_bfloat16 g_zlo [ (size_t)ROWS * ZD ];
__device__ __nv_bfloat16 g_Wlg_hi[ (size_t)ZD * ZD ];    // W_lgssm split (i x m)
__device__ __nv_bfloat16 g_Wlg_lo[ (size_t)ZD * ZD ];
__device__ __nv_bfloat16 g_WihT_hi[ (size_t)G3 * ZD ];   // W_ih transposed (o x m)
__device__ __nv_bfloat16 g_WihT_lo[ (size_t)G3 * ZD ];
__device__ __nv_bfloat16 g_WcT_hi[ (size_t)G3 * ZD ];    // (Wlg@Wih)^T  (o x i)
__device__ __nv_bfloat16 g_WcT_lo[ (size_t)G3 * ZD ];
__device__ float g_GI  [ (size_t)ROWS * G3 ];            // z@W_comb + b_comb (fp32)
__device__ float g_bcomb[G3];
__device__ float g_zb  [ZD];                             // stays zero
__device__ float g_WhhT[ (size_t)G3 * HID ];
__device__ float g_H   [ (size_t)ROWS * HID ];
__device__ float g_D   [ (size_t)ROWS * DEN ];
__device__ float g_hT  [2][HID * BATCH];                 // ping-pong h, [k][b]

// grid-barrier state for the persistent scan
#define NCTA_SCAN 128
__device__ unsigned g_bar_ctr = 0;
__device__ volatile unsigned g_bar_flag = 0;

// ---------------- helpers ---------------------------------------------------
__device__ __forceinline__ uint32_t smem_u32(const void* p) {
    uint32_t a;
    asm("{ .reg .u64 t; cvta.to.shared.u64 t, %1; cvt.u32.u64 %0, t; }"
        : "=r"(a) : "l"(p));
    return a;
}
__device__ __forceinline__ void cp16(uint32_t dst, const void* src) {
    asm volatile(
        "{ .reg .u64 g; cvta.to.global.u64 g, %1; "
        "cp.async.cg.shared.global [%0], [g], 16; }"
        :: "r"(dst), "l"(src) : "memory");
}
__device__ __forceinline__ void cp_commit() {
    asm volatile("cp.async.commit_group;" ::: "memory");
}
template <int N>
__device__ __forceinline__ void cp_wait() {
    asm volatile("cp.async.wait_group %0;" :: "n"(N) : "memory");
}
__device__ __forceinline__ void ldsm_x4(uint32_t* r, uint32_t addr) {
    asm volatile("ldmatrix.sync.aligned.m8n8.x4.shared.b16 {%0,%1,%2,%3}, [%4];"
        : "=r"(r[0]), "=r"(r[1]), "=r"(r[2]), "=r"(r[3]) : "r"(addr));
}
__device__ __forceinline__ void mma16816(float* d, const uint32_t* a,
                                         uint32_t b0, uint32_t b1) {
    asm volatile(
        "mma.sync.aligned.m16n8k16.row.col.f32.bf16.bf16.f32 "
        "{%0,%1,%2,%3}, {%4,%5,%6,%7}, {%8,%9}, {%0,%1,%2,%3};"
        : "+f"(d[0]), "+f"(d[1]), "+f"(d[2]), "+f"(d[3])
        : "r"(a[0]), "r"(a[1]), "r"(a[2]), "r"(a[3]), "r"(b0), "r"(b1));
}
// packed fp32x2 fma (Blackwell base ISA)
__device__ __forceinline__ void ffma2(unsigned long long& d,
                                      unsigned long long a, unsigned long long b) {
    asm("fma.rn.f32x2 %0, %1, %2, %3;" : "=l"(d) : "l"(a), "l"(b), "l"(d));
}
__device__ __forceinline__ unsigned long long splat2(float x) {
    unsigned long long r;
    asm("mov.b64 %0, {%1, %1};" : "=l"(r) : "r"(__float_as_uint(x)));
    return r;
}
__device__ __forceinline__ void unpack2(unsigned long long v, float& lo, float& hi) {
    uint32_t l, h;
    asm("mov.b64 {%0, %1}, %2;" : "=r"(l), "=r"(h) : "l"(v));
    lo = __uint_as_float(l);
    hi = __uint_as_float(h);
}

// ---------------- conversion kernels ---------------------------------------
__global__ __launch_bounds__(256) void conv_split_kernel(
    const float* __restrict__ src, __nv_bfloat16* __restrict__ hi,
    __nv_bfloat16* __restrict__ lo, int n)
{
    for (int i = blockIdx.x * 256 + threadIdx.x; i < n; i += gridDim.x * 256) {
        float x = src[i];
        __nv_bfloat16 h = __float2bfloat16(x);
        hi[i] = h;
        lo[i] = __float2bfloat16(x - __bfloat162float(h));
    }
}

// transpose (K x N fp32) -> (N x K bf16 hi/lo)
__global__ __launch_bounds__(256) void transpose_split_kernel(
    const float* __restrict__ W, __nv_bfloat16* __restrict__ Thi,
    __nv_bfloat16* __restrict__ Tlo, int K, int N)
{
    __shared__ float tile[32][33];
    int tx = threadIdx.x, ty = threadIdx.y;
    int x = blockIdx.x * 32 + tx;
    int y0 = blockIdx.y * 32;
    #pragma unroll
    for (int j = ty; j < 32; j += 8)
        tile[j][tx] = W[(size_t)(y0 + j) * N + x];
    __syncthreads();
    int k = blockIdx.y * 32 + tx;
    int n0 = blockIdx.x * 32;
    #pragma unroll
    for (int j = ty; j < 32; j += 8) {
        float v = tile[tx][j];
        __nv_bfloat16 h = __float2bfloat16(v);
        size_t o = (size_t)(n0 + j) * K + k;
        Thi[o] = h;
        Tlo[o] = __float2bfloat16(v - __bfloat162float(h));
    }
}

__global__ void transpose_whh_kernel(const float* __restrict__ W) {
    __shared__ float tile[32][33];
    int x = blockIdx.x * 32 + threadIdx.x;
    int y0 = blockIdx.y * 32;
    #pragma unroll
    for (int j = threadIdx.y; j < 32; j += 8)
        tile[j][threadIdx.x] = W[(size_t)(y0 + j) * G3 + x];
    __syncthreads();
    int xt  = blockIdx.y * 32 + threadIdx.x;
    int yt0 = blockIdx.x * 32;
    #pragma unroll
    for (int j = threadIdx.y; j < 32; j += 8)
        g_WhhT[(size_t)(yt0 + j) * HID + xt] = tile[threadIdx.x][j];
}

// b_comb[o] = b_ih[o] + sum_m b_lgssm[m] * W_ih[m][o]; grid 48, block 256
__global__ __launch_bounds__(256) void bcomb_kernel(
    const float* __restrict__ W_ih, const float* __restrict__ b_lg,
    const float* __restrict__ b_ih)
{
    __shared__ float red[4][64];
    const int tx = threadIdx.x & 63;
    const int ty = threadIdx.x >> 6;
    const int o = blockIdx.x * 64 + tx;
    float acc = 0.0f;
    for (int m = ty; m < ZD; m += 4)
        acc = fmaf(b_lg[m], W_ih[(size_t)m * G3 + o], acc);
    red[ty][tx] = acc;
    __syncthreads();
    if (ty == 0)
        g_bcomb[o] = b_ih[o] + red[0][tx] + red[1][tx] + red[2][tx] + red[3][tx];
}

// ---------------- split-bf16 mma.sync GEMM (128x256 tile, 512 thr) ----------
// 3-stage pipeline, cp.async issue interleaved into the MMA loop.
#define MMK       ZD               // 4096 for both GEMMs
#define BKC       32               // K per stage (bf16)
#define NC        (MMK / BKC)      // 128 chunks
#define ROWB      80               // smem row stride bytes (conflict-free)
#define A_TILEB   (128 * ROWB)     // 10240
#define B_TILEB   (256 * ROWB)     // 20480
#define STAGEB    (2 * A_TILEB + 2 * B_TILEB)  // 61440
#define NSTAGE    3
#define MM_SMEM   (NSTAGE * STAGEB)            // 184320

__global__ __launch_bounds__(512) void mm_mma_kernel(
    const __nv_bfloat16* __restrict__ Ahi, const __nv_bfloat16* __restrict__ Alo,
    const __nv_bfloat16* __restrict__ Bhi, const __nv_bfloat16* __restrict__ Blo,
    const float* __restrict__ bias,
    __nv_bfloat16* __restrict__ Chi, __nv_bfloat16* __restrict__ Clo,
    int Nglob, int which)
{
    extern __shared__ char smem[];
    const uint32_t sb = smem_u32(smem);
    const int tid  = threadIdx.x;
    const int wid  = tid >> 5;
    const int lane = tid & 31;
    const int wm   = wid & 3;          // 4 m-blocks of 32  -> 128
    const int wn   = wid >> 2;         // 4 n-blocks of 64  -> 256

    const size_t mBase = (size_t)blockIdx.y * 128;
    const size_t nBase = (size_t)blockIdx.x * 256;

    const __nv_bfloat16* tp[4] = { Ahi, Alo, Bhi, Blo };
    const size_t rb[4]  = { mBase, mBase, nBase, nBase };
    const uint32_t toff[4] = { 0, A_TILEB, 2 * A_TILEB, 2 * A_TILEB + B_TILEB };

    // per-thread cp.async assignments: 6 x 16B per thread per chunk
    const __nv_bfloat16* srcs[6];
    uint32_t dsts[6];
    #pragma unroll
    for (int i = 0; i < 6; ++i) {
        const int u   = tid + 512 * i;
        const int r   = u >> 2;
        const int seg = u & 3;
        int tile, lrow;
        if (r < 128)      { tile = 0; lrow = r; }
        else if (r < 256) { tile = 1; lrow = r - 128; }
        else if (r < 512) { tile = 2; lrow = r - 256; }
        else              { tile = 3; lrow = r - 512; }
        srcs[i] = tp[tile] + (rb[tile] + lrow) * MMK + seg * 8;
        dsts[i] = toff[tile] + (uint32_t)lrow * ROWB + seg * 16;
    }

    float acc[2][8][4];
    #pragma unroll
    for (int a = 0; a < 2; ++a)
        #pragma unroll
        for (int b = 0; b < 8; ++b)
            #pragma unroll
            for (int c = 0; c < 4; ++c) acc[a][b][c] = 0.0f;

    const int arow = wm * 32 + (lane & 7) + 8 * ((lane >> 3) & 1);
    const int brow = wn * 64 + (lane & 7) + 8 * (lane >> 4);
    const int acol_half = lane >> 4;
    const int bcol_half = (lane >> 3) & 1;

    // prologue: chunks 0,1 into stages 0,1
    #pragma unroll
    for (int i = 0; i < 6; ++i) cp16(sb + 0 * STAGEB + dsts[i], srcs[i]);
    cp_commit();
    #pragma unroll
    for (int i = 0; i < 6; ++i) cp16(sb + 1 * STAGEB + dsts[i], srcs[i] + BKC);
    cp_commit();
    cp_wait<1>();
    __syncthreads();

    int s = 0;
    for (int c = 0; c < NC; ++c) {
        const uint32_t stB = sb + s * STAGEB;
        const int pf = (s + 2 >= NSTAGE) ? s + 2 - NSTAGE : s + 2;
        const uint32_t pfB = sb + pf * STAGEB;
        const bool do_pf = (c + 2 < NC);
        const size_t pfk = (size_t)(c + 2) * BKC;

        const uint32_t AhB = stB;
        const uint32_t AlB = stB + A_TILEB;
        const uint32_t BhB = stB + 2 * A_TILEB;
        const uint32_t BlB = stB + 2 * A_TILEB + B_TILEB;

        #pragma unroll
        for (int ks = 0; ks < 2; ++ks) {
            const uint32_t acolb = (uint32_t)(16 * ks + 8 * acol_half) * 2;
            const uint32_t bcolb = (uint32_t)(16 * ks + 8 * bcol_half) * 2;
            uint32_t Ah0[4], Ah1[4], Al0[4], Al1[4];
            ldsm_x4(Ah0, AhB + (uint32_t)arow * ROWB + acolb);
            ldsm_x4(Ah1, AhB + (uint32_t)(arow + 16) * ROWB + acolb);
            ldsm_x4(Al0, AlB + (uint32_t)arow * ROWB + acolb);
            ldsm_x4(Al1, AlB + (uint32_t)(arow + 16) * ROWB + acolb);
            #pragma unroll
            for (int nb = 0; nb < 4; ++nb) {
                const uint32_t brb = (uint32_t)(brow + nb * 16) * ROWB + bcolb;
                uint32_t bh[4], bl[4];
                ldsm_x4(bh, BhB + brb);
                ldsm_x4(bl, BlB + brb);
                // interleaved prefetch of chunk c+2 (1 cp16 per MMA group)
                {
                    const int g = ks * 4 + nb;
                    if (g < 6 && do_pf) cp16(pfB + dsts[g], srcs[g] + pfk);
                }
                // Ah x Bh
                mma16816(acc[0][2 * nb],     Ah0, bh[0], bh[1]);
                mma16816(acc[0][2 * nb + 1], Ah0, bh[2], bh[3]);
                mma16816(acc[1][2 * nb],     Ah1, bh[0], bh[1]);
                mma16816(acc[1][2 * nb + 1], Ah1, bh[2], bh[3]);
                // Ah x Bl
                mma16816(acc[0][2 * nb],     Ah0, bl[0], bl[1]);
                mma16816(acc[0][2 * nb + 1], Ah0, bl[2], bl[3]);
                mma16816(acc[1][2 * nb],     Ah1, bl[0], bl[1]);
                mma16816(acc[1][2 * nb + 1], Ah1, bl[2], bl[3]);
                // Al x Bh
                mma16816(acc[0][2 * nb],     Al0, bh[0], bh[1]);
                mma16816(acc[0][2 * nb + 1], Al0, bh[2], bh[3]);
                mma16816(acc[1][2 * nb],     Al1, bh[0], bh[1]);
                mma16816(acc[1][2 * nb + 1], Al1, bh[2], bh[3]);
            }
        }
        cp_commit();
        cp_wait<1>();       // chunk c+1 resident (c+2's group may be in flight)
        __syncthreads();
        s = (s + 1 == NSTAGE) ? 0 : s + 1;
    }

    // epilogue
    const int rrow = (lane >> 2);
    const int ccol = 2 * (lane & 3);
    #pragma unroll
    for (int mi = 0; mi < 2; ++mi) {
        const size_t r0 = mBase + wm * 32 + mi * 16 + rrow;
        #pragma unroll
        for (int n8 = 0; n8 < 8; ++n8) {
            const int col = (int)nBase + wn * 64 + n8 * 8 + ccol;
            const float bz0 = __ldg(&bias[col]);
            const float bz1 = __ldg(&bias[col + 1]);
            const float* f = acc[mi][n8];
            if (which == 0) {
                #pragma unroll
                for (int h = 0; h < 2; ++h) {
                    const size_t r = r0 + 8 * h;
                    float v0 = f[2 * h]     + bz0;
                    float v1 = f[2 * h + 1] + bz1;
                    __nv_bfloat16 h0 = __float2bfloat16(v0);
                    __nv_bfloat16 h1 = __float2bfloat16(v1);
                    __nv_bfloat16 l0 = __float2bfloat16(v0 - __bfloat162float(h0));
                    __nv_bfloat16 l1 = __float2bfloat16(v1 - __bfloat162float(h1));
                    uint32_t hp = ((uint32_t)__bfloat16_as_ushort(h1) << 16) |
                                  (uint32_t)__bfloat16_as_ushort(h0);
                    uint32_t lp = ((uint32_t)__bfloat16_as_ushort(l1) << 16) |
                                  (uint32_t)__bfloat16_as_ushort(l0);
                    *(uint32_t*)&Chi[r * (size_t)Nglob + col] = hp;
                    *(uint32_t*)&Clo[r * (size_t)Nglob + col] = lp;
                }
            } else {
                #pragma unroll
                for (int h = 0; h < 2; ++h) {
                    const size_t r = r0 + 8 * h;
                    float2 v = make_float2(f[2 * h] + bz0, f[2 * h + 1] + bz1);
                    *(float2*)&g_GI[r * (size_t)Nglob + col] = v;
                }
            }
        }
    }
}

// ---------------- persistent GRU scan (f32x2 inner product) -----------------
__global__ __launch_bounds__(256) void gru_scan_kernel(const float* __restrict__ b_hh)
{
    __shared__ alignas(16) float sh[HID * BATCH];    // h_prev, [k][b]
    __shared__ unsigned s_sense;
    const int tid  = threadIdx.x;
    const int warp = tid >> 5;
    const int lane = tid & 31;
    const int j = blockIdx.x * 8 + warp;

    // weights -> registers (coalesced, once)
    float w0[32], w1[32], w2[32];
    {
        const float* W0 = g_WhhT + (size_t)j * HID;
        const float* W1 = g_WhhT + (size_t)(HID + j) * HID;
        const float* W2 = g_WhhT + (size_t)(2 * HID + j) * HID;
        #pragma unroll
        for (int it = 0; it < 32; ++it) {
            const int k = lane + 32 * it;
            w0[it] = W0[k]; w1[it] = W1[k]; w2[it] = W2[k];
        }
    }
    const float bh0 = b_hh[j];
    const float bh1 = b_hh[HID + j];
    const float bh2 = b_hh[2 * HID + j];

    if (tid == 0) s_sense = g_bar_flag;
    for (int i = tid; i < HID * BATCH; i += 256) sh[i] = 0.0f;   // h0 = 0
    __syncthreads();
    unsigned sense = s_sense;

    for (int t = 0; t < WIN; ++t) {
        float pir = 0.f, piu = 0.f, pin = 0.f;
        if (lane < 8) {
            const size_t r = (size_t)lane * WIN + t;
            const float* gi = g_GI + r * G3;
            pir = gi[j];
            piu = gi[HID + j];
            pin = gi[2 * HID + j];
        }

        unsigned long long A0[4], A1[4], A2[4];
        #pragma unroll
        for (int p = 0; p < 4; ++p) { A0[p] = 0ull; A1[p] = 0ull; A2[p] = 0ull; }

        #pragma unroll 8
        for (int it = 0; it < 32; ++it) {
            const int k = lane + 32 * it;
            const ulonglong2* hp = (const ulonglong2*)&sh[k * 8];
            const ulonglong2 hA = hp[0];     // (b0,b1),(b2,b3)
            const ulonglong2 hB = hp[1];     // (b4,b5),(b6,b7)
            const unsigned long long wr2 = splat2(w0[it]);
            const unsigned long long wu2 = splat2(w1[it]);
            const unsigned long long wn2 = splat2(w2[it]);
            ffma2(A0[0], wr2, hA.x); ffma2(A0[1], wr2, hA.y);
            ffma2(A0[2], wr2, hB.x); ffma2(A0[3], wr2, hB.y);
            ffma2(A1[0], wu2, hA.x); ffma2(A1[1], wu2, hA.y);
            ffma2(A1[2], wu2, hB.x); ffma2(A1[3], wu2, hB.y);
            ffma2(A2[0], wn2, hA.x); ffma2(A2[1], wn2, hA.y);
            ffma2(A2[2], wn2, hB.x); ffma2(A2[3], wn2, hB.y);
        }

        float a0[8], a1[8], a2[8];
        #pragma unroll
        for (int p = 0; p < 4; ++p) {
            unpack2(A0[p], a0[2 * p], a0[2 * p + 1]);
            unpack2(A1[p], a1[2 * p], a1[2 * p + 1]);
            unpack2(A2[p], a2[2 * p], a2[2 * p + 1]);
        }

        #pragma unroll
        for (int off = 16; off > 0; off >>= 1) {
            #pragma unroll
            for (int b = 0; b < 8; ++b) {
                a0[b] += __shfl_xor_sync(0xffffffffu, a0[b], off);
                a1[b] += __shfl_xor_sync(0xffffffffu, a1[b], off);
                a2[b] += __shfl_xor_sync(0xffffffffu, a2[b], off);
            }
        }

        if (lane < 8) {
            float hr = 0.f, hu = 0.f, hn = 0.f;
            #pragma unroll
            for (int b = 0; b < 8; ++b)
                if (b == lane) { hr = a0[b]; hu = a1[b]; hn = a2[b]; }
            hr += bh0; hu += bh1; hn += bh2;
            const float rg = 1.0f / (1.0f + expf(-(pir + hr)));
            const float ug = 1.0f / (1.0f + expf(-(piu + hu)));
            const float ng = tanhf(fmaf(rg, hn, pin));
            const float hp = sh[j * 8 + lane];
            const float hnew = (1.0f - ug) * ng + ug * hp;
            g_hT[t & 1][j * 8 + lane] = hnew;
            g_H[((size_t)lane * WIN + t) * HID + j] = hnew;
        }
        __syncthreads();

        // grid barrier (sense-reversing); single release/acquire fence per CTA
        if (tid == 0) {
            __threadfence();
            const unsigned old = atomicAdd(&g_bar_ctr, 1u);
            if (old == NCTA_SCAN - 1) {
                g_bar_ctr = 0;
                __threadfence();
                g_bar_flag = sense ^ 1u;
            }
            while (g_bar_flag == sense) { __nanosleep(32); }
            __threadfence();
        }
        __syncthreads();
        sense ^= 1u;

        if (t + 1 < WIN) {
            const float4* src = (const float4*)g_hT[t & 1];
            float4* dst = (float4*)sh;
            #pragma unroll
            for (int i = tid; i < HID * BATCH / 4; i += 256) dst[i] = src[i];
            __syncthreads();
        }
    }
}

// ---------------- dense + heads (unchanged) --------------------------------
__global__ __launch_bounds__(128) void dense_kernel(
    const float* __restrict__ Wd, const float* __restrict__ bd)
{
    __shared__ float sh[8 * HID];
    const int r0 = blockIdx.x * 8;
    for (int i = threadIdx.x; i < 8 * HID; i += 128)
        sh[i] = g_H[(size_t)r0 * HID + i];
    __syncthreads();

    const int c = threadIdx.x;
    if (c < DEN) {
        float acc[8];
        #pragma unroll
        for (int i = 0; i < 8; ++i) acc[i] = bd[c];
        #pragma unroll 4
        for (int k = 0; k < HID; ++k) {
            const float w = Wd[k * DEN + c];
            #pragma unroll
            for (int i = 0; i < 8; ++i)
                acc[i] = fmaf(sh[i * HID + k], w, acc[i]);
        }
        #pragma unroll
        for (int i = 0; i < 8; ++i)
            g_D[(size_t)(r0 + i) * DEN + c] = acc[i];
    }
}

__global__ __launch_bounds__(128) void heads_kernel(
    const float* __restrict__ W_mu, const float* __restrict__ b_mu,
    const float* __restrict__ W_sg, const float* __restrict__ b_sg,
    const float* __restrict__ noise, float* __restrict__ out)
{
    __shared__ float sh[16 * DEN];
    const int r0 = blockIdx.x * 16;
    for (int i = threadIdx.x; i < 16 * DEN; i += 128)
        sh[i] = g_D[(size_t)r0 * DEN + i];
    __syncthreads();

    const int c = threadIdx.x;
    if (c < OUT_D) {
        float am[16], as[16];
        #pragma unroll
        for (int i = 0; i < 16; ++i) { am[i] = b_mu[c]; as[i] = b_sg[c]; }
        #pragma unroll 2
        for (int k = 0; k < DEN; ++k) {
            const float wm = W_mu[k * OUT_D + c];
            const float ws = W_sg[k * OUT_D + c];
            #pragma unroll
            for (int i = 0; i < 16; ++i) {
                const float d = sh[i * DEN + k];
                am[i] = fmaf(d, wm, am[i]);
                as[i] = fmaf(d, ws, as[i]);
            }
        }
        #pragma unroll
        for (int i = 0; i < 16; ++i) {
            const size_t r = (size_t)(r0 + i);
            const float x = as[i];
            const float sp = fmaxf(x, 0.0f) + log1pf(expf(-fabsf(x)));
            out[r * OUT_D + c] = fmaf(sp, noise[r * OUT_D + c], am[i]);
        }
    }
}

// ---------------------------------------------------------------------------
extern "C" void kernel_launch(void* const* d_in, const int* in_sizes, int n_in,
                              void* d_out, int out_size)
{
    const float* z        = (const float*)d_in[0];
    const float* noise    = (const float*)d_in[1];
    const float* W_lgssm  = (const float*)d_in[2];
    const float* b_lgssm  = (const float*)d_in[3];
    const float* W_ih     = (const float*)d_in[4];
    const float* b_ih     = (const float*)d_in[5];
    const float* W_hh     = (const float*)d_in[6];
    const float* b_hh     = (const float*)d_in[7];
    const float* W_dense  = (const float*)d_in[8];
    const float* b_dense  = (const float*)d_in[9];
    const float* W_mu     = (const float*)d_in[10];
    const float* b_mu     = (const float*)d_in[11];
    const float* W_sigma  = (const float*)d_in[12];
    const float* b_sigma  = (const float*)d_in[13];
    float* out = (float*)d_out;

    static int attr_done = 0;
    if (!attr_done) {
        cudaFuncSetAttribute(mm_mma_kernel,
                             cudaFuncAttributeMaxDynamicSharedMemorySize, MM_SMEM);
        attr_done = 1;
    }

    __nv_bfloat16 *p_zhi, *p_zlo, *p_Wlg_hi, *p_Wlg_lo, *p_Wih_hi, *p_Wih_lo;
    __nv_bfloat16 *p_WcT_hi, *p_WcT_lo;
    float *p_bcomb, *p_zb;
    cudaGetSymbolAddress((void**)&p_zhi,    g_zhi);
    cudaGetSymbolAddress((void**)&p_zlo,    g_zlo);
    cudaGetSymbolAddress((void**)&p_Wlg_hi, g_Wlg_hi);
    cudaGetSymbolAddress((void**)&p_Wlg_lo, g_Wlg_lo);
    cudaGetSymbolAddress((void**)&p_Wih_hi, g_WihT_hi);
    cudaGetSymbolAddress((void**)&p_Wih_lo, g_WihT_lo);
    cudaGetSymbolAddress((void**)&p_WcT_hi, g_WcT_hi);
    cudaGetSymbolAddress((void**)&p_WcT_lo, g_WcT_lo);
    cudaGetSymbolAddress((void**)&p_bcomb,  g_bcomb);
    cudaGetSymbolAddress((void**)&p_zb,     g_zb);

    // 1-3: weight conversions + bias fold (also positions mm fold at slot 4
    //      for ncu capture)
    conv_split_kernel<<<2048, 256>>>(W_lgssm, p_Wlg_hi, p_Wlg_lo, ZD * ZD);
    transpose_split_kernel<<<dim3(G3 / 32, ZD / 32), dim3(32, 8)>>>(
        W_ih, p_Wih_hi, p_Wih_lo, ZD, G3);
    bcomb_kernel<<<G3 / 64, 256>>>(W_ih, b_lgssm, b_ih);

    // 4: fold GEMM: W_combT[o][i] = sum_m W_ihT[o][m] * W_lgssm[i][m]
    mm_mma_kernel<<<dim3(ZD / 256, G3 / 128), 512, MM_SMEM>>>(
        p_Wih_hi, p_Wih_lo, p_Wlg_hi, p_Wlg_lo, p_zb, p_WcT_hi, p_WcT_lo, ZD, 0);

    // 5: z split
    conv_split_kernel<<<2048, 256>>>(z, p_zhi, p_zlo, ROWS * ZD);

    // 6: data GEMM: GI[r][o] = sum_i z[r][i] * W_combT[o][i] + b_comb[o]
    mm_mma_kernel<<<dim3(G3 / 256, ROWS / 128), 512, MM_SMEM>>>(
        p_zhi, p_zlo, p_WcT_hi, p_WcT_lo, p_bcomb, nullptr, nullptr, G3, 1);

    // 7: W_hh transpose for the scan
    transpose_whh_kernel<<<dim3(G3 / 32, HID / 32), dim3(32, 8)>>>(W_hh);

    // 8: persistent GRU scan
    gru_scan_kernel<<<NCTA_SCAN, 256>>>(b_hh);

    // 9-10: deferred output path
    dense_kernel<<<ROWS / 8, 128>>>(W_dense, b_dense);
    heads_kernel<<<ROWS / 16, 128>>>(W_mu, b_mu, W_sigma, b_sigma, noise, out);
}